// round 1
// baseline (speedup 1.0000x reference)
#include <cuda_runtime.h>
#include <math.h>

#define SEQ 2048
#define DMODEL 4096
#define NHEADS 32
#define NKVH 8
#define HDIM 128
#define DFF 16384

// ---------------- scratch (device globals; no runtime allocation) ----------------
__device__ float g_xn[SEQ * DMODEL];          // rmsnorm1 output
__device__ float g_q[SEQ * NHEADS * HDIM];    // q proj
__device__ float g_k[SEQ * NKVH * HDIM];      // k proj
__device__ float g_v[SEQ * NKVH * HDIM];      // v proj
__device__ float g_attn[SEQ * NHEADS * HDIM]; // attention output (bqhd layout)
__device__ float g_h[SEQ * DMODEL];           // residual + attn@wo
__device__ float g_x2[SEQ * DMODEL];          // rmsnorm2 output
__device__ float g_gate[SEQ * DFF];           // gate proj (then silu(g)*u)
__device__ float g_up[SEQ * DFF];             // up proj

// ---------------- RMSNorm: one block per row ----------------
__global__ void rmsnorm_kernel(const float* __restrict__ x, const float* __restrict__ w,
                               float* __restrict__ y) {
    const int row = blockIdx.x;
    const float* xr = x + (size_t)row * DMODEL;
    float* yr = y + (size_t)row * DMODEL;
    float ss = 0.f;
#pragma unroll
    for (int i = 0; i < DMODEL / 1024; i++) {
        int idx = i * 1024 + threadIdx.x * 4;
        float4 v = *(const float4*)(xr + idx);
        ss += v.x * v.x + v.y * v.y + v.z * v.z + v.w * v.w;
    }
#pragma unroll
    for (int off = 16; off; off >>= 1) ss += __shfl_xor_sync(0xffffffffu, ss, off);
    __shared__ float red[8];
    __shared__ float s_scale;
    if ((threadIdx.x & 31) == 0) red[threadIdx.x >> 5] = ss;
    __syncthreads();
    if (threadIdx.x == 0) {
        float tot = 0.f;
#pragma unroll
        for (int i = 0; i < 8; i++) tot += red[i];
        s_scale = rsqrtf(tot / (float)DMODEL + 1e-5f);
    }
    __syncthreads();
    float sc = s_scale;
#pragma unroll
    for (int i = 0; i < DMODEL / 1024; i++) {
        int idx = i * 1024 + threadIdx.x * 4;
        float4 v = *(const float4*)(xr + idx);
        float4 wv = *(const float4*)(w + idx);
        v.x = v.x * sc * wv.x;
        v.y = v.y * sc * wv.y;
        v.z = v.z * sc * wv.z;
        v.w = v.w * sc * wv.w;
        *(float4*)(yr + idx) = v;
    }
}

// ---------------- SGEMM: C = A(MxK,row) @ B(KxN,row) [+ add] ----------------
// BM=BN=128, BK=8, 256 threads, 8x8 per thread.
template <bool ADD>
__global__ void sgemm_kernel(const float* __restrict__ A, const float* __restrict__ B,
                             float* __restrict__ C, const float* __restrict__ add,
                             int M, int N, int K) {
    __shared__ float As[8][128];
    __shared__ float Bs[8][128];
    const int bx = blockIdx.x;  // N tile
    const int by = blockIdx.y;  // M tile
    const int tid = threadIdx.x;
    const int row0 = (tid / 16) * 8;
    const int col0 = (tid % 16) * 8;

    float acc[8][8];
#pragma unroll
    for (int i = 0; i < 8; i++)
#pragma unroll
        for (int j = 0; j < 8; j++) acc[i][j] = 0.f;

    const float* Ab = A + (size_t)by * 128 * K;
    const float* Bb = B + (size_t)bx * 128;
    const int ar = tid >> 1, ak = (tid & 1) * 4;
    const int br = tid >> 5, bn = (tid & 31) * 4;

    for (int k0 = 0; k0 < K; k0 += 8) {
        float4 av = *(const float4*)(Ab + (size_t)ar * K + k0 + ak);
        As[ak + 0][ar] = av.x;
        As[ak + 1][ar] = av.y;
        As[ak + 2][ar] = av.z;
        As[ak + 3][ar] = av.w;
        float4 bv = *(const float4*)(Bb + (size_t)(k0 + br) * N + bn);
        *(float4*)(&Bs[br][bn]) = bv;
        __syncthreads();
#pragma unroll
        for (int kk = 0; kk < 8; kk++) {
            float ra[8], rb[8];
            *(float4*)&ra[0] = *(const float4*)&As[kk][row0];
            *(float4*)&ra[4] = *(const float4*)&As[kk][row0 + 4];
            *(float4*)&rb[0] = *(const float4*)&Bs[kk][col0];
            *(float4*)&rb[4] = *(const float4*)&Bs[kk][col0 + 4];
#pragma unroll
            for (int i = 0; i < 8; i++)
#pragma unroll
                for (int j = 0; j < 8; j++) acc[i][j] += ra[i] * rb[j];
        }
        __syncthreads();
    }

#pragma unroll
    for (int i = 0; i < 8; i++) {
        int r = by * 128 + row0 + i;
        float* Crow = C + (size_t)r * N + bx * 128 + col0;
        const float* Arow = ADD ? (add + (size_t)r * N + bx * 128 + col0) : (const float*)0;
#pragma unroll
        for (int j = 0; j < 8; j += 4) {
            float4 v = make_float4(acc[i][j], acc[i][j + 1], acc[i][j + 2], acc[i][j + 3]);
            if (ADD) {
                float4 w = *(const float4*)(Arow + j);
                v.x += w.x;
                v.y += w.y;
                v.z += w.z;
                v.w += w.w;
            }
            *(float4*)(Crow + j) = v;
        }
    }
}

// ---------------- RoPE + l2-norm, one block per (s, head), 64 threads ----------------
__global__ void rope_l2_kernel(float* __restrict__ x, const float* __restrict__ cosb,
                               const float* __restrict__ sinb, int nheads) {
    const int s = blockIdx.x, h = blockIdx.y, t = threadIdx.x;
    float* p = x + ((size_t)s * nheads + h) * HDIM;
    float2 xv = *(float2*)(p + 2 * t);
    float c = cosb[s * (HDIM / 2) + t];
    float sn = sinb[s * (HDIM / 2) + t];
    float o_r = xv.x * c - xv.y * sn;
    float o_i = xv.x * sn + xv.y * c;
    float ss = o_r * o_r + o_i * o_i;
#pragma unroll
    for (int off = 16; off; off >>= 1) ss += __shfl_xor_sync(0xffffffffu, ss, off);
    __shared__ float wsum[2];
    if ((t & 31) == 0) wsum[t >> 5] = ss;
    __syncthreads();
    float r = rsqrtf((wsum[0] + wsum[1]) / (float)HDIM + 1e-5f);
    *(float2*)(p + 2 * t) = make_float2(o_r * r, o_i * r);
}

// ---------------- Flash attention (fp32), 64x64 tiles, causal mask inline ----------------
#define FLASH_SMEM ((64 * 132 * 2 + 64 * 128 + 64 * 65 + 192) * 4)

__global__ void flash_attn_kernel(const float* __restrict__ q, const float* __restrict__ k,
                                  const float* __restrict__ v, float* __restrict__ o) {
    extern __shared__ float sm[];
    float* Qs = sm;                 // [64][132]
    float* Ks = Qs + 64 * 132;      // [64][132]
    float* Vs = Ks + 64 * 132;      // [64][128]
    float* Ss = Vs + 64 * 128;      // [64][65]
    float* m_s = Ss + 64 * 65;      // [64]
    float* l_s = m_s + 64;          // [64]
    float* corr_s = l_s + 64;       // [64]

    const int qb = blockIdx.x, h = blockIdx.y;
    const int kvh = h >> 2;  // n_rep = 4
    const int tid = threadIdx.x;
    const float scale = 0.08838834764831845f;  // 128^-0.5

    // load Q tile
#pragma unroll
    for (int it = 0; it < 16; it++) {
        int idx = it * 128 + tid;
        int r = idx >> 5, c4 = (idx & 31) << 2;
        float4 val = *(const float4*)(q + (size_t)(qb * 64 + r) * (NHEADS * HDIM) + h * HDIM + c4);
        *(float4*)(Qs + r * 132 + c4) = val;
    }
    if (tid < 64) {
        m_s[tid] = -1e30f;
        l_s[tid] = 0.f;
    }

    float Oa[64];
#pragma unroll
    for (int c = 0; c < 64; c++) Oa[c] = 0.f;

    const int sr0 = (tid >> 3) * 4;
    const int sc0 = tid & 7;
    const int orow = tid & 63;
    const int oc0 = (tid >> 6) * 64;

    for (int j = 0; j <= qb; j++) {
        // load K/V tiles
#pragma unroll
        for (int it = 0; it < 16; it++) {
            int idx = it * 128 + tid;
            int r = idx >> 5, c4 = (idx & 31) << 2;
            size_t src = (size_t)(j * 64 + r) * (NKVH * HDIM) + kvh * HDIM + c4;
            *(float4*)(Ks + r * 132 + c4) = *(const float4*)(k + src);
            *(float4*)(Vs + r * 128 + c4) = *(const float4*)(v + src);
        }
        __syncthreads();

        // scores: S = Q K^T (rows sr0..+3, cols sc0 + 8*jj)
        float sacc[4][8];
#pragma unroll
        for (int i = 0; i < 4; i++)
#pragma unroll
            for (int jj = 0; jj < 8; jj++) sacc[i][jj] = 0.f;
#pragma unroll 4
        for (int d = 0; d < HDIM; d++) {
            float kf[8];
#pragma unroll
            for (int jj = 0; jj < 8; jj++) kf[jj] = Ks[(sc0 + 8 * jj) * 132 + d];
#pragma unroll
            for (int i = 0; i < 4; i++) {
                float qf = Qs[(sr0 + i) * 132 + d];
#pragma unroll
                for (int jj = 0; jj < 8; jj++) sacc[i][jj] += qf * kf[jj];
            }
        }
#pragma unroll
        for (int i = 0; i < 4; i++) {
            int r = sr0 + i;
            int qidx = qb * 64 + r;
#pragma unroll
            for (int jj = 0; jj < 8; jj++) {
                int c = sc0 + 8 * jj;
                int kidx = j * 64 + c;
                float sval = sacc[i][jj] * scale + (kidx <= qidx ? 0.f : -1e9f);
                Ss[r * 65 + c] = sval;
            }
        }
        __syncthreads();

        // online softmax (row leaders)
        if (tid < 64) {
            int r = tid;
            float rmax = -1e30f;
#pragma unroll 8
            for (int c = 0; c < 64; c++) rmax = fmaxf(rmax, Ss[r * 65 + c]);
            float newm = fmaxf(m_s[r], rmax);
            float corr = expf(m_s[r] - newm);
            float lsum = 0.f;
#pragma unroll 8
            for (int c = 0; c < 64; c++) {
                float p = expf(Ss[r * 65 + c] - newm);
                Ss[r * 65 + c] = p;
                lsum += p;
            }
            l_s[r] = l_s[r] * corr + lsum;
            m_s[r] = newm;
            corr_s[r] = corr;
        }
        __syncthreads();

        // O = O*corr + P @ V  (thread owns row orow, 64 cols starting at oc0)
        float corr = corr_s[orow];
#pragma unroll
        for (int c = 0; c < 64; c++) Oa[c] *= corr;
#pragma unroll 2
        for (int kk = 0; kk < 64; kk++) {
            float p = Ss[orow * 65 + kk];
#pragma unroll
            for (int c = 0; c < 64; c += 4) {
                float4 vv = *(const float4*)(Vs + kk * 128 + oc0 + c);
                Oa[c] += p * vv.x;
                Oa[c + 1] += p * vv.y;
                Oa[c + 2] += p * vv.z;
                Oa[c + 3] += p * vv.w;
            }
        }
        __syncthreads();
    }

    float linv = 1.f / l_s[orow];
#pragma unroll
    for (int c = 0; c < 64; c += 4) {
        float4 ov = make_float4(Oa[c] * linv, Oa[c + 1] * linv, Oa[c + 2] * linv, Oa[c + 3] * linv);
        *(float4*)(o + (size_t)(qb * 64 + orow) * (NHEADS * HDIM) + h * HDIM + oc0 + c) = ov;
    }
}

// ---------------- silu(gate) * up, in place into gate ----------------
__global__ void silu_mul_kernel(float* __restrict__ g, const float* __restrict__ u, long long n4) {
    for (long long i = (long long)blockIdx.x * blockDim.x + threadIdx.x; i < n4;
         i += (long long)gridDim.x * blockDim.x) {
        float4 gv = ((float4*)g)[i];
        float4 uv = ((const float4*)u)[i];
        gv.x = gv.x / (1.f + expf(-gv.x)) * uv.x;
        gv.y = gv.y / (1.f + expf(-gv.y)) * uv.y;
        gv.z = gv.z / (1.f + expf(-gv.z)) * uv.z;
        gv.w = gv.w / (1.f + expf(-gv.w)) * uv.w;
        ((float4*)g)[i] = gv;
    }
}

// ---------------- launch ----------------
extern "C" void kernel_launch(void* const* d_in, const int* in_sizes, int n_in,
                              void* d_out, int out_size) {
    const float* hidden = (const float*)d_in[0];
    // d_in[1] = attn_mask: exact 0 / -1e9 causal mask; reproduced inline instead.
    const float* fcos = (const float*)d_in[2];
    const float* fsin = (const float*)d_in[3];
    const float* ln1 = (const float*)d_in[4];
    const float* wq = (const float*)d_in[5];
    const float* wk = (const float*)d_in[6];
    const float* wv = (const float*)d_in[7];
    const float* wo = (const float*)d_in[8];
    const float* ln2 = (const float*)d_in[9];
    const float* gate_w = (const float*)d_in[10];
    const float* up_w = (const float*)d_in[11];
    const float* down_w = (const float*)d_in[12];
    float* out = (float*)d_out;

    float *xn, *q, *k, *v, *attn, *h, *x2, *gate, *up;
    cudaGetSymbolAddress((void**)&xn, g_xn);
    cudaGetSymbolAddress((void**)&q, g_q);
    cudaGetSymbolAddress((void**)&k, g_k);
    cudaGetSymbolAddress((void**)&v, g_v);
    cudaGetSymbolAddress((void**)&attn, g_attn);
    cudaGetSymbolAddress((void**)&h, g_h);
    cudaGetSymbolAddress((void**)&x2, g_x2);
    cudaGetSymbolAddress((void**)&gate, g_gate);
    cudaGetSymbolAddress((void**)&up, g_up);

    cudaFuncSetAttribute(flash_attn_kernel, cudaFuncAttributeMaxDynamicSharedMemorySize,
                         FLASH_SMEM);

    // 1) rmsnorm1
    rmsnorm_kernel<<<SEQ, 256>>>(hidden, ln1, xn);
    // 2) QKV projections
    sgemm_kernel<false><<<dim3((NHEADS * HDIM) / 128, SEQ / 128), 256>>>(
        xn, wq, q, (const float*)0, SEQ, NHEADS * HDIM, DMODEL);
    sgemm_kernel<false><<<dim3((NKVH * HDIM) / 128, SEQ / 128), 256>>>(
        xn, wk, k, (const float*)0, SEQ, NKVH * HDIM, DMODEL);
    sgemm_kernel<false><<<dim3((NKVH * HDIM) / 128, SEQ / 128), 256>>>(
        xn, wv, v, (const float*)0, SEQ, NKVH * HDIM, DMODEL);
    // 3) RoPE + l2norm
    rope_l2_kernel<<<dim3(SEQ, NHEADS), 64>>>(q, fcos, fsin, NHEADS);
    rope_l2_kernel<<<dim3(SEQ, NKVH), 64>>>(k, fcos, fsin, NKVH);
    // 4) flash attention
    flash_attn_kernel<<<dim3(SEQ / 64, NHEADS), 128, FLASH_SMEM>>>(q, k, v, attn);
    // 5) O projection + residual
    sgemm_kernel<true><<<dim3(DMODEL / 128, SEQ / 128), 256>>>(attn, wo, h, hidden, SEQ, DMODEL,
                                                               NHEADS * HDIM);
    // 6) rmsnorm2
    rmsnorm_kernel<<<SEQ, 256>>>(h, ln2, x2);
    // 7) gate / up projections
    sgemm_kernel<false><<<dim3(DFF / 128, SEQ / 128), 256>>>(x2, gate_w, gate, (const float*)0,
                                                             SEQ, DFF, DMODEL);
    sgemm_kernel<false><<<dim3(DFF / 128, SEQ / 128), 256>>>(x2, up_w, up, (const float*)0, SEQ,
                                                             DFF, DMODEL);
    // 8) silu(gate)*up
    silu_mul_kernel<<<4096, 256>>>(gate, up, (long long)SEQ * DFF / 4);
    // 9) down projection + residual -> output
    sgemm_kernel<true><<<dim3(DMODEL / 128, SEQ / 128), 256>>>(gate, down_w, out, h, SEQ, DMODEL,
                                                               DFF);
}

// round 3
// speedup vs baseline: 2.1401x; 2.1401x over previous
#include <cuda_runtime.h>
#include <cuda_bf16.h>
#include <cstdint>
#include <math.h>

#define SEQ 2048
#define DMODEL 4096
#define NHEADS 32
#define NKVH 8
#define HDIM 128
#define DFF 16384

// ===================== scratch =====================
__device__ float g_q[SEQ * NHEADS * HDIM];
__device__ float g_k[SEQ * NKVH * HDIM];
__device__ float g_v[SEQ * NKVH * HDIM];
__device__ float g_attn[SEQ * NHEADS * HDIM];
__device__ float g_h[SEQ * DMODEL];
__device__ float g_ff0[SEQ * DFF];
__device__ float g_ff1[SEQ * DFF];

__device__ __nv_bfloat16 g_xnh[SEQ * DMODEL], g_xnl[SEQ * DMODEL];
__device__ __nv_bfloat16 g_attnh[SEQ * DMODEL], g_attnl[SEQ * DMODEL];
__device__ __nv_bfloat16 g_x2h[SEQ * DMODEL], g_x2l[SEQ * DMODEL];
__device__ __nv_bfloat16 g_ffh[SEQ * DFF], g_ffl[SEQ * DFF];

__device__ __nv_bfloat16 g_wqth[DMODEL * DMODEL], g_wqtl[DMODEL * DMODEL];
__device__ __nv_bfloat16 g_wkth[NKVH * HDIM * DMODEL], g_wktl[NKVH * HDIM * DMODEL];
__device__ __nv_bfloat16 g_wvth[NKVH * HDIM * DMODEL], g_wvtl[NKVH * HDIM * DMODEL];
__device__ __nv_bfloat16 g_woth[DMODEL * DMODEL], g_wotl[DMODEL * DMODEL];
__device__ __nv_bfloat16 g_gth[DFF * DMODEL], g_gtl[DFF * DMODEL];
__device__ __nv_bfloat16 g_uth[DFF * DMODEL], g_utl[DFF * DMODEL];
__device__ __nv_bfloat16 g_dth[DMODEL * DFF], g_dtl[DMODEL * DFF];

// ===================== helpers =====================
__device__ __forceinline__ uint32_t smem_to_u32(const void* p) {
    uint32_t a;
    asm("{ .reg .u64 t; cvta.to.shared.u64 t, %1; cvt.u32.u64 %0, t; }" : "=r"(a) : "l"(p));
    return a;
}
__device__ __forceinline__ void cp_async16(uint32_t saddr, const void* gaddr) {
    asm volatile("cp.async.cg.shared.global [%0], [%1], 16;" ::"r"(saddr), "l"(gaddr));
}
__device__ __forceinline__ void cp_commit() { asm volatile("cp.async.commit_group;" ::: "memory"); }
#define CP_WAIT(N) asm volatile("cp.async.wait_group %0;" ::"n"(N) : "memory")

__device__ __forceinline__ void ldsm_x4(uint32_t addr, uint32_t& r0, uint32_t& r1, uint32_t& r2,
                                        uint32_t& r3) {
    asm volatile("ldmatrix.sync.aligned.m8n8.x4.shared.b16 {%0,%1,%2,%3}, [%4];"
                 : "=r"(r0), "=r"(r1), "=r"(r2), "=r"(r3)
                 : "r"(addr));
}
__device__ __forceinline__ void mma16816(float* c, uint32_t a0, uint32_t a1, uint32_t a2,
                                         uint32_t a3, uint32_t b0, uint32_t b1) {
    asm volatile(
        "mma.sync.aligned.m16n8k16.row.col.f32.bf16.bf16.f32 "
        "{%0,%1,%2,%3}, {%4,%5,%6,%7}, {%8,%9}, {%0,%1,%2,%3};"
        : "+f"(c[0]), "+f"(c[1]), "+f"(c[2]), "+f"(c[3])
        : "r"(a0), "r"(a1), "r"(a2), "r"(a3), "r"(b0), "r"(b1));
}

__device__ __forceinline__ void split2(float a, float b, __nv_bfloat162& h2, __nv_bfloat162& l2) {
    __nv_bfloat16 ha = __float2bfloat16(a), hb = __float2bfloat16(b);
    __nv_bfloat16 la = __float2bfloat16(a - __bfloat162float(ha));
    __nv_bfloat16 lb = __float2bfloat16(b - __bfloat162float(hb));
    h2 = __halves2bfloat162(ha, hb);
    l2 = __halves2bfloat162(la, lb);
}

// ===================== RMSNorm + split =====================
__global__ void rmsnorm_split_kernel(const float* __restrict__ x, const float* __restrict__ w,
                                     __nv_bfloat16* __restrict__ yh,
                                     __nv_bfloat16* __restrict__ yl) {
    const int row = blockIdx.x;
    const float* xr = x + (size_t)row * DMODEL;
    float ss = 0.f;
#pragma unroll
    for (int i = 0; i < DMODEL / 1024; i++) {
        int idx = i * 1024 + threadIdx.x * 4;
        float4 v = *(const float4*)(xr + idx);
        ss += v.x * v.x + v.y * v.y + v.z * v.z + v.w * v.w;
    }
#pragma unroll
    for (int off = 16; off; off >>= 1) ss += __shfl_xor_sync(0xffffffffu, ss, off);
    __shared__ float red[8];
    __shared__ float s_scale;
    if ((threadIdx.x & 31) == 0) red[threadIdx.x >> 5] = ss;
    __syncthreads();
    if (threadIdx.x == 0) {
        float tot = 0.f;
#pragma unroll
        for (int i = 0; i < 8; i++) tot += red[i];
        s_scale = rsqrtf(tot / (float)DMODEL + 1e-5f);
    }
    __syncthreads();
    float sc = s_scale;
#pragma unroll
    for (int i = 0; i < DMODEL / 1024; i++) {
        int idx = i * 1024 + threadIdx.x * 4;
        float4 v = *(const float4*)(xr + idx);
        float4 wv = *(const float4*)(w + idx);
        v.x *= sc * wv.x;
        v.y *= sc * wv.y;
        v.z *= sc * wv.z;
        v.w *= sc * wv.w;
        __nv_bfloat162 h0, l0, h1, l1;
        split2(v.x, v.y, h0, l0);
        split2(v.z, v.w, h1, l1);
        __nv_bfloat162* ph = (__nv_bfloat162*)(yh + (size_t)row * DMODEL + idx);
        __nv_bfloat162* pl = (__nv_bfloat162*)(yl + (size_t)row * DMODEL + idx);
        ph[0] = h0;
        ph[1] = h1;
        pl[0] = l0;
        pl[1] = l1;
    }
}

// ===================== generic split =====================
__global__ void split_kernel(const float* __restrict__ x, __nv_bfloat16* __restrict__ h,
                             __nv_bfloat16* __restrict__ l, long long n4) {
    for (long long i = (long long)blockIdx.x * blockDim.x + threadIdx.x; i < n4;
         i += (long long)gridDim.x * blockDim.x) {
        float4 v = ((const float4*)x)[i];
        __nv_bfloat162 h0, l0, h1, l1;
        split2(v.x, v.y, h0, l0);
        split2(v.z, v.w, h1, l1);
        ((__nv_bfloat162*)h)[2 * i] = h0;
        ((__nv_bfloat162*)h)[2 * i + 1] = h1;
        ((__nv_bfloat162*)l)[2 * i] = l0;
        ((__nv_bfloat162*)l)[2 * i + 1] = l1;
    }
}

// ===================== silu(g)*u + split =====================
__global__ void silu_mul_split_kernel(const float* __restrict__ g, const float* __restrict__ u,
                                      __nv_bfloat16* __restrict__ h, __nv_bfloat16* __restrict__ l,
                                      long long n4) {
    for (long long i = (long long)blockIdx.x * blockDim.x + threadIdx.x; i < n4;
         i += (long long)gridDim.x * blockDim.x) {
        float4 gv = ((const float4*)g)[i];
        float4 uv = ((const float4*)u)[i];
        gv.x = gv.x / (1.f + expf(-gv.x)) * uv.x;
        gv.y = gv.y / (1.f + expf(-gv.y)) * uv.y;
        gv.z = gv.z / (1.f + expf(-gv.z)) * uv.z;
        gv.w = gv.w / (1.f + expf(-gv.w)) * uv.w;
        __nv_bfloat162 h0, l0, h1, l1;
        split2(gv.x, gv.y, h0, l0);
        split2(gv.z, gv.w, h1, l1);
        ((__nv_bfloat162*)h)[2 * i] = h0;
        ((__nv_bfloat162*)h)[2 * i + 1] = h1;
        ((__nv_bfloat162*)l)[2 * i] = l0;
        ((__nv_bfloat162*)l)[2 * i + 1] = l1;
    }
}

// ===================== transpose + split: B[K,N] fp32 -> T[N,K] bf16 hi/lo =====================
__global__ void transpose_split_kernel(const float* __restrict__ B, __nv_bfloat16* __restrict__ Th,
                                       __nv_bfloat16* __restrict__ Tl, int Kdim, int Ndim) {
    __shared__ float t[32][33];
    const int n0 = blockIdx.x * 32, k0 = blockIdx.y * 32;
    const int tx = threadIdx.x, ty = threadIdx.y;
#pragma unroll
    for (int i = 0; i < 32; i += 8) t[ty + i][tx] = B[(size_t)(k0 + ty + i) * Ndim + n0 + tx];
    __syncthreads();
#pragma unroll
    for (int i = 0; i < 32; i += 8) {
        float v = t[tx][ty + i];
        __nv_bfloat16 hv = __float2bfloat16(v);
        __nv_bfloat16 lv = __float2bfloat16(v - __bfloat162float(hv));
        size_t o = (size_t)(n0 + ty + i) * Kdim + k0 + tx;
        Th[o] = hv;
        Tl[o] = lv;
    }
}

// ===================== bf16x3 GEMM via mma.sync =====================
// C[M,N] = (Ah+Al)[M,K] @ (Bh+Bl)[N,K]^T (+ add). fp32 accum.
// BM=128, BN=128, BK=32, 8 warps (4m x 2n), warp tile 32x64.
#define BM 128
#define BN 128
#define BK 32
#define SKB 80  // padded row stride in BYTES (40 halves)
#define STG_B (BM * SKB)        // 10240 bytes per array per stage
#define O_AH 0
#define O_AL (2 * STG_B)
#define O_BH (4 * STG_B)
#define O_BL (6 * STG_B)
#define GEMM_SMEM (8 * STG_B)   // 81920 bytes

__device__ __forceinline__ void gemm_ldg_stage(uint32_t sb, const __nv_bfloat16* Ah,
                                               const __nv_bfloat16* Al, const __nv_bfloat16* Bh,
                                               const __nv_bfloat16* Bl, int K, int m0, int n0,
                                               int k0, int stage, int tid) {
    const uint32_t so_base = stage * STG_B;
#pragma unroll
    for (int i = 0; i < 2; i++) {
        int id = i * 256 + tid;
        int r = id >> 2, c = id & 3;
        uint32_t sa = so_base + r * SKB + c * 16;
        size_t ga = (size_t)(m0 + r) * K + k0 + c * 8;
        cp_async16(sb + O_AH + sa, Ah + ga);
        cp_async16(sb + O_AL + sa, Al + ga);
        size_t gb = (size_t)(n0 + r) * K + k0 + c * 8;
        cp_async16(sb + O_BH + sa, Bh + gb);
        cp_async16(sb + O_BL + sa, Bl + gb);
    }
}

template <int ADD>
__global__ void __launch_bounds__(256, 1)
    gemm_bf16x3_kernel(const __nv_bfloat16* __restrict__ Ah, const __nv_bfloat16* __restrict__ Al,
                       const __nv_bfloat16* __restrict__ Bh, const __nv_bfloat16* __restrict__ Bl,
                       float* __restrict__ C, const float* __restrict__ add, int M, int N, int K) {
    extern __shared__ char smem[];
    const uint32_t sb = smem_to_u32(smem);
    const int tid = threadIdx.x;
    const int wid = tid >> 5, lane = tid & 31;
    const int wm = wid >> 1, wn = wid & 1;
    const int m0 = blockIdx.y * BM, n0 = blockIdx.x * BN;

    float acc[2][8][4];
#pragma unroll
    for (int a = 0; a < 2; a++)
#pragma unroll
        for (int b = 0; b < 8; b++)
#pragma unroll
            for (int c = 0; c < 4; c++) acc[a][b][c] = 0.f;

    const int nk = K / BK;
    gemm_ldg_stage(sb, Ah, Al, Bh, Bl, K, m0, n0, 0, 0, tid);
    cp_commit();

    // ldmatrix lane addressing: row = lane&15, col_half_offset = (lane>>4)*8
    const int lrow = lane & 15;
    const int lcol = (lane >> 4) * 8;  // in halves

    for (int kt = 0; kt < nk; kt++) {
        if (kt + 1 < nk) {
            gemm_ldg_stage(sb, Ah, Al, Bh, Bl, K, m0, n0, (kt + 1) * BK, (kt + 1) & 1, tid);
            cp_commit();
            CP_WAIT(1);
        } else {
            CP_WAIT(0);
        }
        __syncthreads();

        const uint32_t st = (kt & 1) * STG_B;
#pragma unroll
        for (int ks = 0; ks < 2; ks++) {
            const uint32_t kh = ks * 16;  // k offset in halves
            uint32_t ah[2][4], al[2][4];
#pragma unroll
            for (int mt = 0; mt < 2; mt++) {
                uint32_t arow = wm * 32 + mt * 16 + lrow;
                uint32_t ao = st + arow * SKB + (kh + lcol) * 2;
                ldsm_x4(sb + O_AH + ao, ah[mt][0], ah[mt][1], ah[mt][2], ah[mt][3]);
                ldsm_x4(sb + O_AL + ao, al[mt][0], al[mt][1], al[mt][2], al[mt][3]);
            }
#pragma unroll
            for (int ng = 0; ng < 4; ng++) {
                uint32_t brow = wn * 64 + ng * 16 + lrow;
                uint32_t bo = st + brow * SKB + (kh + lcol) * 2;
                uint32_t bh[4], bl[4];
                ldsm_x4(sb + O_BH + bo, bh[0], bh[1], bh[2], bh[3]);
                ldsm_x4(sb + O_BL + bo, bl[0], bl[1], bl[2], bl[3]);
#pragma unroll
                for (int mt = 0; mt < 2; mt++) {
#pragma unroll
                    for (int half = 0; half < 2; half++) {
                        float* cc = acc[mt][ng * 2 + half];
                        uint32_t b0h = half ? bh[1] : bh[0], b1h = half ? bh[3] : bh[2];
                        uint32_t b0l = half ? bl[1] : bl[0], b1l = half ? bl[3] : bl[2];
                        mma16816(cc, ah[mt][0], ah[mt][1], ah[mt][2], ah[mt][3], b0h, b1h);
                        mma16816(cc, ah[mt][0], ah[mt][1], ah[mt][2], ah[mt][3], b0l, b1l);
                        mma16816(cc, al[mt][0], al[mt][1], al[mt][2], al[mt][3], b0h, b1h);
                    }
                }
            }
        }
        __syncthreads();
    }

    // epilogue
    const int g = lane >> 2, tg = lane & 3;
#pragma unroll
    for (int mt = 0; mt < 2; mt++) {
#pragma unroll
        for (int nt = 0; nt < 8; nt++) {
            int row = m0 + wm * 32 + mt * 16 + g;
            int col = n0 + wn * 64 + nt * 8 + tg * 2;
            float* cc = acc[mt][nt];
            float2 v0 = make_float2(cc[0], cc[1]);
            float2 v1 = make_float2(cc[2], cc[3]);
            if (ADD) {
                float2 a0 = *(const float2*)(add + (size_t)row * N + col);
                float2 a1 = *(const float2*)(add + (size_t)(row + 8) * N + col);
                v0.x += a0.x;
                v0.y += a0.y;
                v1.x += a1.x;
                v1.y += a1.y;
            }
            *(float2*)(C + (size_t)row * N + col) = v0;
            *(float2*)(C + (size_t)(row + 8) * N + col) = v1;
        }
    }
}

// ===================== RoPE + l2-norm =====================
__global__ void rope_l2_kernel(float* __restrict__ x, const float* __restrict__ cosb,
                               const float* __restrict__ sinb, int nheads) {
    const int s = blockIdx.x, h = blockIdx.y, t = threadIdx.x;
    float* p = x + ((size_t)s * nheads + h) * HDIM;
    float2 xv = *(float2*)(p + 2 * t);
    float c = cosb[s * (HDIM / 2) + t];
    float sn = sinb[s * (HDIM / 2) + t];
    float o_r = xv.x * c - xv.y * sn;
    float o_i = xv.x * sn + xv.y * c;
    float ss = o_r * o_r + o_i * o_i;
#pragma unroll
    for (int off = 16; off; off >>= 1) ss += __shfl_xor_sync(0xffffffffu, ss, off);
    __shared__ float wsum[2];
    if ((t & 31) == 0) wsum[t >> 5] = ss;
    __syncthreads();
    float r = rsqrtf((wsum[0] + wsum[1]) / (float)HDIM + 1e-5f);
    *(float2*)(p + 2 * t) = make_float2(o_r * r, o_i * r);
}

// ===================== Flash attention (fp32) =====================
#define FLASH_SMEM ((64 * 132 * 2 + 64 * 128 + 64 * 65 + 192) * 4)

__global__ void flash_attn_kernel(const float* __restrict__ q, const float* __restrict__ k,
                                  const float* __restrict__ v, float* __restrict__ o) {
    extern __shared__ float sm[];
    float* Qs = sm;
    float* Ks = Qs + 64 * 132;
    float* Vs = Ks + 64 * 132;
    float* Ss = Vs + 64 * 128;
    float* m_s = Ss + 64 * 65;
    float* l_s = m_s + 64;
    float* corr_s = l_s + 64;

    const int qb = blockIdx.x, h = blockIdx.y;
    const int kvh = h >> 2;
    const int tid = threadIdx.x;
    const float scale = 0.08838834764831845f;

#pragma unroll
    for (int it = 0; it < 16; it++) {
        int idx = it * 128 + tid;
        int r = idx >> 5, c4 = (idx & 31) << 2;
        float4 val = *(const float4*)(q + (size_t)(qb * 64 + r) * (NHEADS * HDIM) + h * HDIM + c4);
        *(float4*)(Qs + r * 132 + c4) = val;
    }
    if (tid < 64) {
        m_s[tid] = -1e30f;
        l_s[tid] = 0.f;
    }

    float Oa[64];
#pragma unroll
    for (int c = 0; c < 64; c++) Oa[c] = 0.f;

    const int sr0 = (tid >> 3) * 4;
    const int sc0 = tid & 7;
    const int orow = tid & 63;
    const int oc0 = (tid >> 6) * 64;

    for (int j = 0; j <= qb; j++) {
#pragma unroll
        for (int it = 0; it < 16; it++) {
            int idx = it * 128 + tid;
            int r = idx >> 5, c4 = (idx & 31) << 2;
            size_t src = (size_t)(j * 64 + r) * (NKVH * HDIM) + kvh * HDIM + c4;
            *(float4*)(Ks + r * 132 + c4) = *(const float4*)(k + src);
            *(float4*)(Vs + r * 128 + c4) = *(const float4*)(v + src);
        }
        __syncthreads();

        float sacc[4][8];
#pragma unroll
        for (int i = 0; i < 4; i++)
#pragma unroll
            for (int jj = 0; jj < 8; jj++) sacc[i][jj] = 0.f;
#pragma unroll 4
        for (int d = 0; d < HDIM; d++) {
            float kf[8];
#pragma unroll
            for (int jj = 0; jj < 8; jj++) kf[jj] = Ks[(sc0 + 8 * jj) * 132 + d];
#pragma unroll
            for (int i = 0; i < 4; i++) {
                float qf = Qs[(sr0 + i) * 132 + d];
#pragma unroll
                for (int jj = 0; jj < 8; jj++) sacc[i][jj] += qf * kf[jj];
            }
        }
#pragma unroll
        for (int i = 0; i < 4; i++) {
            int r = sr0 + i;
            int qidx = qb * 64 + r;
#pragma unroll
            for (int jj = 0; jj < 8; jj++) {
                int c = sc0 + 8 * jj;
                int kidx = j * 64 + c;
                float sval = sacc[i][jj] * scale + (kidx <= qidx ? 0.f : -1e9f);
                Ss[r * 65 + c] = sval;
            }
        }
        __syncthreads();

        if (tid < 64) {
            int r = tid;
            float rmax = -1e30f;
#pragma unroll 8
            for (int c = 0; c < 64; c++) rmax = fmaxf(rmax, Ss[r * 65 + c]);
            float newm = fmaxf(m_s[r], rmax);
            float corr = expf(m_s[r] - newm);
            float lsum = 0.f;
#pragma unroll 8
            for (int c = 0; c < 64; c++) {
                float p = expf(Ss[r * 65 + c] - newm);
                Ss[r * 65 + c] = p;
                lsum += p;
            }
            l_s[r] = l_s[r] * corr + lsum;
            m_s[r] = newm;
            corr_s[r] = corr;
        }
        __syncthreads();

        float corr = corr_s[orow];
#pragma unroll
        for (int c = 0; c < 64; c++) Oa[c] *= corr;
#pragma unroll 2
        for (int kk = 0; kk < 64; kk++) {
            float p = Ss[orow * 65 + kk];
#pragma unroll
            for (int c = 0; c < 64; c += 4) {
                float4 vv = *(const float4*)(Vs + kk * 128 + oc0 + c);
                Oa[c] += p * vv.x;
                Oa[c + 1] += p * vv.y;
                Oa[c + 2] += p * vv.z;
                Oa[c + 3] += p * vv.w;
            }
        }
        __syncthreads();
    }

    float linv = 1.f / l_s[orow];
#pragma unroll
    for (int c = 0; c < 64; c += 4) {
        float4 ov = make_float4(Oa[c] * linv, Oa[c + 1] * linv, Oa[c + 2] * linv, Oa[c + 3] * linv);
        *(float4*)(o + (size_t)(qb * 64 + orow) * (NHEADS * HDIM) + h * HDIM + oc0 + c) = ov;
    }
}

// ===================== launch =====================
extern "C" void kernel_launch(void* const* d_in, const int* in_sizes, int n_in,
                              void* d_out, int out_size) {
    const float* hidden = (const float*)d_in[0];
    const float* fcos = (const float*)d_in[2];
    const float* fsin = (const float*)d_in[3];
    const float* ln1 = (const float*)d_in[4];
    const float* wq = (const float*)d_in[5];
    const float* wk = (const float*)d_in[6];
    const float* wv = (const float*)d_in[7];
    const float* wo = (const float*)d_in[8];
    const float* ln2 = (const float*)d_in[9];
    const float* gate_w = (const float*)d_in[10];
    const float* up_w = (const float*)d_in[11];
    const float* down_w = (const float*)d_in[12];
    float* out = (float*)d_out;

    float *q, *k, *v, *attn, *h, *ff0, *ff1;
    cudaGetSymbolAddress((void**)&q, g_q);
    cudaGetSymbolAddress((void**)&k, g_k);
    cudaGetSymbolAddress((void**)&v, g_v);
    cudaGetSymbolAddress((void**)&attn, g_attn);
    cudaGetSymbolAddress((void**)&h, g_h);
    cudaGetSymbolAddress((void**)&ff0, g_ff0);
    cudaGetSymbolAddress((void**)&ff1, g_ff1);
    __nv_bfloat16 *xnh, *xnl, *attnh, *attnl, *x2h, *x2l, *ffh, *ffl;
    cudaGetSymbolAddress((void**)&xnh, g_xnh);
    cudaGetSymbolAddress((void**)&xnl, g_xnl);
    cudaGetSymbolAddress((void**)&attnh, g_attnh);
    cudaGetSymbolAddress((void**)&attnl, g_attnl);
    cudaGetSymbolAddress((void**)&x2h, g_x2h);
    cudaGetSymbolAddress((void**)&x2l, g_x2l);
    cudaGetSymbolAddress((void**)&ffh, g_ffh);
    cudaGetSymbolAddress((void**)&ffl, g_ffl);
    __nv_bfloat16 *wqth, *wqtl, *wkth, *wktl, *wvth, *wvtl, *woth, *wotl, *gth, *gtl, *uth, *utl,
        *dth, *dtl;
    cudaGetSymbolAddress((void**)&wqth, g_wqth);
    cudaGetSymbolAddress((void**)&wqtl, g_wqtl);
    cudaGetSymbolAddress((void**)&wkth, g_wkth);
    cudaGetSymbolAddress((void**)&wktl, g_wktl);
    cudaGetSymbolAddress((void**)&wvth, g_wvth);
    cudaGetSymbolAddress((void**)&wvtl, g_wvtl);
    cudaGetSymbolAddress((void**)&woth, g_woth);
    cudaGetSymbolAddress((void**)&wotl, g_wotl);
    cudaGetSymbolAddress((void**)&gth, g_gth);
    cudaGetSymbolAddress((void**)&gtl, g_gtl);
    cudaGetSymbolAddress((void**)&uth, g_uth);
    cudaGetSymbolAddress((void**)&utl, g_utl);
    cudaGetSymbolAddress((void**)&dth, g_dth);
    cudaGetSymbolAddress((void**)&dtl, g_dtl);

    cudaFuncSetAttribute(flash_attn_kernel, cudaFuncAttributeMaxDynamicSharedMemorySize,
                         FLASH_SMEM);
    cudaFuncSetAttribute(gemm_bf16x3_kernel<0>, cudaFuncAttributeMaxDynamicSharedMemorySize,
                         GEMM_SMEM);
    cudaFuncSetAttribute(gemm_bf16x3_kernel<1>, cudaFuncAttributeMaxDynamicSharedMemorySize,
                         GEMM_SMEM);

    dim3 tb(32, 8);
    // weight transpose + split
    transpose_split_kernel<<<dim3(DMODEL / 32, DMODEL / 32), tb>>>(wq, wqth, wqtl, DMODEL, DMODEL);
    transpose_split_kernel<<<dim3((NKVH * HDIM) / 32, DMODEL / 32), tb>>>(wk, wkth, wktl, DMODEL,
                                                                          NKVH * HDIM);
    transpose_split_kernel<<<dim3((NKVH * HDIM) / 32, DMODEL / 32), tb>>>(wv, wvth, wvtl, DMODEL,
                                                                          NKVH * HDIM);
    transpose_split_kernel<<<dim3(DMODEL / 32, DMODEL / 32), tb>>>(wo, woth, wotl, DMODEL, DMODEL);
    transpose_split_kernel<<<dim3(DFF / 32, DMODEL / 32), tb>>>(gate_w, gth, gtl, DMODEL, DFF);
    transpose_split_kernel<<<dim3(DFF / 32, DMODEL / 32), tb>>>(up_w, uth, utl, DMODEL, DFF);
    transpose_split_kernel<<<dim3(DMODEL / 32, DFF / 32), tb>>>(down_w, dth, dtl, DFF, DMODEL);

    // rmsnorm1 + split
    rmsnorm_split_kernel<<<SEQ, 256>>>(hidden, ln1, xnh, xnl);
    // QKV
    gemm_bf16x3_kernel<0><<<dim3((NHEADS * HDIM) / BN, SEQ / BM), 256, GEMM_SMEM>>>(
        xnh, xnl, wqth, wqtl, q, q, SEQ, NHEADS * HDIM, DMODEL);
    gemm_bf16x3_kernel<0><<<dim3((NKVH * HDIM) / BN, SEQ / BM), 256, GEMM_SMEM>>>(
        xnh, xnl, wkth, wktl, k, k, SEQ, NKVH * HDIM, DMODEL);
    gemm_bf16x3_kernel<0><<<dim3((NKVH * HDIM) / BN, SEQ / BM), 256, GEMM_SMEM>>>(
        xnh, xnl, wvth, wvtl, v, v, SEQ, NKVH * HDIM, DMODEL);
    // RoPE + l2norm
    rope_l2_kernel<<<dim3(SEQ, NHEADS), 64>>>(q, fcos, fsin, NHEADS);
    rope_l2_kernel<<<dim3(SEQ, NKVH), 64>>>(k, fcos, fsin, NKVH);
    // attention
    flash_attn_kernel<<<dim3(SEQ / 64, NHEADS), 128, FLASH_SMEM>>>(q, k, v, attn);
    // O proj + residual
    split_kernel<<<2048, 256>>>(attn, attnh, attnl, (long long)SEQ * DMODEL / 4);
    gemm_bf16x3_kernel<1><<<dim3(DMODEL / BN, SEQ / BM), 256, GEMM_SMEM>>>(
        attnh, attnl, woth, wotl, h, hidden, SEQ, DMODEL, DMODEL);
    // rmsnorm2 + split
    rmsnorm_split_kernel<<<SEQ, 256>>>(h, ln2, x2h, x2l);
    // gate / up
    gemm_bf16x3_kernel<0><<<dim3(DFF / BN, SEQ / BM), 256, GEMM_SMEM>>>(
        x2h, x2l, gth, gtl, ff0, ff0, SEQ, DFF, DMODEL);
    gemm_bf16x3_kernel<0><<<dim3(DFF / BN, SEQ / BM), 256, GEMM_SMEM>>>(
        x2h, x2l, uth, utl, ff1, ff1, SEQ, DFF, DMODEL);
    // silu*up + split
    silu_mul_split_kernel<<<4096, 256>>>(ff0, ff1, ffh, ffl, (long long)SEQ * DFF / 4);
    // down + residual
    gemm_bf16x3_kernel<1><<<dim3(DMODEL / BN, SEQ / BM), 256, GEMM_SMEM>>>(
        ffh, ffl, dth, dtl, out, h, SEQ, DMODEL, DFF);
}

// round 4
// speedup vs baseline: 2.3819x; 1.1130x over previous
#include <cuda_runtime.h>
#include <cuda_bf16.h>
#include <cstdint>
#include <math.h>

#define SEQ 2048
#define DMODEL 4096
#define NHEADS 32
#define NKVH 8
#define HDIM 128
#define DFF 16384
#define NQKV 6144   // 4096 q + 1024 k + 1024 v
#define NGU 32768   // 16384 gate + 16384 up

// ===================== scratch =====================
__device__ float g_qkv[SEQ * NQKV];
__device__ float g_h[SEQ * DMODEL];
__device__ float g_gu[SEQ * NGU];

__device__ __nv_bfloat16 g_xnh[SEQ * DMODEL], g_xnl[SEQ * DMODEL];
__device__ __nv_bfloat16 g_qh[SEQ * NHEADS * HDIM], g_ql[SEQ * NHEADS * HDIM];
__device__ __nv_bfloat16 g_kh[SEQ * NKVH * HDIM], g_kl[SEQ * NKVH * HDIM];
__device__ __nv_bfloat16 g_vh[SEQ * NKVH * HDIM], g_vl[SEQ * NKVH * HDIM];
__device__ __nv_bfloat16 g_attnh[SEQ * DMODEL], g_attnl[SEQ * DMODEL];
__device__ __nv_bfloat16 g_x2h[SEQ * DMODEL], g_x2l[SEQ * DMODEL];
__device__ __nv_bfloat16 g_ffh[SEQ * DFF], g_ffl[SEQ * DFF];

__device__ __nv_bfloat16 g_wqkvth[NQKV * DMODEL], g_wqkvtl[NQKV * DMODEL];
__device__ __nv_bfloat16 g_woth[DMODEL * DMODEL], g_wotl[DMODEL * DMODEL];
__device__ __nv_bfloat16 g_guth[(size_t)NGU * DMODEL], g_gutl[(size_t)NGU * DMODEL];
__device__ __nv_bfloat16 g_dth[(size_t)DMODEL * DFF], g_dtl[(size_t)DMODEL * DFF];

// ===================== helpers =====================
__device__ __forceinline__ uint32_t smem_to_u32(const void* p) {
    uint32_t a;
    asm("{ .reg .u64 t; cvta.to.shared.u64 t, %1; cvt.u32.u64 %0, t; }" : "=r"(a) : "l"(p));
    return a;
}
__device__ __forceinline__ void cp_async16(uint32_t saddr, const void* gaddr) {
    asm volatile("cp.async.cg.shared.global [%0], [%1], 16;" ::"r"(saddr), "l"(gaddr));
}
__device__ __forceinline__ void cp_commit() { asm volatile("cp.async.commit_group;" ::: "memory"); }
#define CP_WAIT(N) asm volatile("cp.async.wait_group %0;" ::"n"(N) : "memory")

__device__ __forceinline__ void ldsm_x4(uint32_t addr, uint32_t& r0, uint32_t& r1, uint32_t& r2,
                                        uint32_t& r3) {
    asm volatile("ldmatrix.sync.aligned.m8n8.x4.shared.b16 {%0,%1,%2,%3}, [%4];"
                 : "=r"(r0), "=r"(r1), "=r"(r2), "=r"(r3)
                 : "r"(addr));
}
__device__ __forceinline__ void ldsm_x4_t(uint32_t addr, uint32_t& r0, uint32_t& r1, uint32_t& r2,
                                          uint32_t& r3) {
    asm volatile("ldmatrix.sync.aligned.m8n8.x4.trans.shared.b16 {%0,%1,%2,%3}, [%4];"
                 : "=r"(r0), "=r"(r1), "=r"(r2), "=r"(r3)
                 : "r"(addr));
}
__device__ __forceinline__ void mma16816(float* c, uint32_t a0, uint32_t a1, uint32_t a2,
                                         uint32_t a3, uint32_t b0, uint32_t b1) {
    asm volatile(
        "mma.sync.aligned.m16n8k16.row.col.f32.bf16.bf16.f32 "
        "{%0,%1,%2,%3}, {%4,%5,%6,%7}, {%8,%9}, {%0,%1,%2,%3};"
        : "+f"(c[0]), "+f"(c[1]), "+f"(c[2]), "+f"(c[3])
        : "r"(a0), "r"(a1), "r"(a2), "r"(a3), "r"(b0), "r"(b1));
}

__device__ __forceinline__ void split2(float a, float b, __nv_bfloat162& h2, __nv_bfloat162& l2) {
    __nv_bfloat16 ha = __float2bfloat16(a), hb = __float2bfloat16(b);
    __nv_bfloat16 la = __float2bfloat16(a - __bfloat162float(ha));
    __nv_bfloat16 lb = __float2bfloat16(b - __bfloat162float(hb));
    h2 = __halves2bfloat162(ha, hb);
    l2 = __halves2bfloat162(la, lb);
}
__device__ __forceinline__ void pack2(float x, float y, uint32_t& hi, uint32_t& lo) {
    __nv_bfloat162 h2, l2;
    split2(x, y, h2, l2);
    hi = *(uint32_t*)&h2;
    lo = *(uint32_t*)&l2;
}

// ===================== RMSNorm + split =====================
__global__ void rmsnorm_split_kernel(const float* __restrict__ x, const float* __restrict__ w,
                                     __nv_bfloat16* __restrict__ yh,
                                     __nv_bfloat16* __restrict__ yl) {
    const int row = blockIdx.x;
    const float* xr = x + (size_t)row * DMODEL;
    float ss = 0.f;
#pragma unroll
    for (int i = 0; i < DMODEL / 1024; i++) {
        int idx = i * 1024 + threadIdx.x * 4;
        float4 v = *(const float4*)(xr + idx);
        ss += v.x * v.x + v.y * v.y + v.z * v.z + v.w * v.w;
    }
#pragma unroll
    for (int off = 16; off; off >>= 1) ss += __shfl_xor_sync(0xffffffffu, ss, off);
    __shared__ float red[8];
    __shared__ float s_scale;
    if ((threadIdx.x & 31) == 0) red[threadIdx.x >> 5] = ss;
    __syncthreads();
    if (threadIdx.x == 0) {
        float tot = 0.f;
#pragma unroll
        for (int i = 0; i < 8; i++) tot += red[i];
        s_scale = rsqrtf(tot / (float)DMODEL + 1e-5f);
    }
    __syncthreads();
    float sc = s_scale;
#pragma unroll
    for (int i = 0; i < DMODEL / 1024; i++) {
        int idx = i * 1024 + threadIdx.x * 4;
        float4 v = *(const float4*)(xr + idx);
        float4 wv = *(const float4*)(w + idx);
        v.x *= sc * wv.x;
        v.y *= sc * wv.y;
        v.z *= sc * wv.z;
        v.w *= sc * wv.w;
        __nv_bfloat162 h0, l0, h1, l1;
        split2(v.x, v.y, h0, l0);
        split2(v.z, v.w, h1, l1);
        __nv_bfloat162* ph = (__nv_bfloat162*)(yh + (size_t)row * DMODEL + idx);
        __nv_bfloat162* pl = (__nv_bfloat162*)(yl + (size_t)row * DMODEL + idx);
        ph[0] = h0;
        ph[1] = h1;
        pl[0] = l0;
        pl[1] = l1;
    }
}

// ===================== V split (from fused qkv buffer) =====================
__global__ void vsplit_kernel(const float* __restrict__ qkv, __nv_bfloat16* __restrict__ vh,
                              __nv_bfloat16* __restrict__ vl) {
    int i = blockIdx.x * blockDim.x + threadIdx.x;  // over SEQ*1024/4
    int s = i >> 8;
    int c = (i & 255) * 4;
    float4 v = *(const float4*)(qkv + (size_t)s * NQKV + 5120 + c);
    __nv_bfloat162 h0, l0, h1, l1;
    split2(v.x, v.y, h0, l0);
    split2(v.z, v.w, h1, l1);
    size_t o = (size_t)s * 1024 + c;
    *(__nv_bfloat162*)(vh + o) = h0;
    *(__nv_bfloat162*)(vh + o + 2) = h1;
    *(__nv_bfloat162*)(vl + o) = l0;
    *(__nv_bfloat162*)(vl + o + 2) = l1;
}

// ===================== silu(gate)*up + split (fused gu buffer) =====================
__global__ void silu_mul_split_kernel(const float* __restrict__ gu, __nv_bfloat16* __restrict__ h,
                                      __nv_bfloat16* __restrict__ l) {
    const long long n4 = (long long)SEQ * DFF / 4;
    for (long long i = (long long)blockIdx.x * blockDim.x + threadIdx.x; i < n4;
         i += (long long)gridDim.x * blockDim.x) {
        int s = (int)(i / (DFF / 4));
        int c = (int)(i % (DFF / 4)) * 4;
        float4 gv = *(const float4*)(gu + (size_t)s * NGU + c);
        float4 uv = *(const float4*)(gu + (size_t)s * NGU + DFF + c);
        gv.x = gv.x / (1.f + expf(-gv.x)) * uv.x;
        gv.y = gv.y / (1.f + expf(-gv.y)) * uv.y;
        gv.z = gv.z / (1.f + expf(-gv.z)) * uv.z;
        gv.w = gv.w / (1.f + expf(-gv.w)) * uv.w;
        __nv_bfloat162 h0, l0, h1, l1;
        split2(gv.x, gv.y, h0, l0);
        split2(gv.z, gv.w, h1, l1);
        size_t o = (size_t)s * DFF + c;
        *(__nv_bfloat162*)(h + o) = h0;
        *(__nv_bfloat162*)(h + o + 2) = h1;
        *(__nv_bfloat162*)(l + o) = l0;
        *(__nv_bfloat162*)(l + o + 2) = l1;
    }
}

// ===================== transpose + split =====================
__global__ void transpose_split_kernel(const float* __restrict__ B, __nv_bfloat16* __restrict__ Th,
                                       __nv_bfloat16* __restrict__ Tl, int Kdim, int Ndim) {
    __shared__ float t[32][33];
    const int n0 = blockIdx.x * 32, k0 = blockIdx.y * 32;
    const int tx = threadIdx.x, ty = threadIdx.y;
#pragma unroll
    for (int i = 0; i < 32; i += 8) t[ty + i][tx] = B[(size_t)(k0 + ty + i) * Ndim + n0 + tx];
    __syncthreads();
#pragma unroll
    for (int i = 0; i < 32; i += 8) {
        float v = t[tx][ty + i];
        __nv_bfloat16 hv = __float2bfloat16(v);
        __nv_bfloat16 lv = __float2bfloat16(v - __bfloat162float(hv));
        size_t o = (size_t)(n0 + ty + i) * Kdim + k0 + tx;
        Th[o] = hv;
        Tl[o] = lv;
    }
}

// ===================== bf16x3 GEMM via mma.sync =====================
#define BM 128
#define BN 128
#define BK 32
#define SKB 80
#define STG_B (BM * SKB)
#define O_AH 0
#define O_AL (2 * STG_B)
#define O_BH (4 * STG_B)
#define O_BL (6 * STG_B)
#define GEMM_SMEM (8 * STG_B)

__device__ __forceinline__ void gemm_ldg_stage(uint32_t sb, const __nv_bfloat16* Ah,
                                               const __nv_bfloat16* Al, const __nv_bfloat16* Bh,
                                               const __nv_bfloat16* Bl, int K, int m0, int n0,
                                               int k0, int stage, int tid) {
    const uint32_t so_base = stage * STG_B;
#pragma unroll
    for (int i = 0; i < 2; i++) {
        int id = i * 256 + tid;
        int r = id >> 2, c = id & 3;
        uint32_t sa = so_base + r * SKB + c * 16;
        size_t ga = (size_t)(m0 + r) * K + k0 + c * 8;
        cp_async16(sb + O_AH + sa, Ah + ga);
        cp_async16(sb + O_AL + sa, Al + ga);
        size_t gb = (size_t)(n0 + r) * K + k0 + c * 8;
        cp_async16(sb + O_BH + sa, Bh + gb);
        cp_async16(sb + O_BL + sa, Bl + gb);
    }
}

template <int ADD>
__global__ void __launch_bounds__(256, 1)
    gemm_bf16x3_kernel(const __nv_bfloat16* __restrict__ Ah, const __nv_bfloat16* __restrict__ Al,
                       const __nv_bfloat16* __restrict__ Bh, const __nv_bfloat16* __restrict__ Bl,
                       float* __restrict__ C, const float* __restrict__ add, int M, int N, int K) {
    extern __shared__ char smem[];
    const uint32_t sb = smem_to_u32(smem);
    const int tid = threadIdx.x;
    const int wid = tid >> 5, lane = tid & 31;
    const int wm = wid >> 1, wn = wid & 1;
    const int m0 = blockIdx.y * BM, n0 = blockIdx.x * BN;

    float acc[2][8][4];
#pragma unroll
    for (int a = 0; a < 2; a++)
#pragma unroll
        for (int b = 0; b < 8; b++)
#pragma unroll
            for (int c = 0; c < 4; c++) acc[a][b][c] = 0.f;

    const int nk = K / BK;
    gemm_ldg_stage(sb, Ah, Al, Bh, Bl, K, m0, n0, 0, 0, tid);
    cp_commit();

    const int lrow = lane & 15;
    const int lcol = (lane >> 4) * 8;

    for (int kt = 0; kt < nk; kt++) {
        if (kt + 1 < nk) {
            gemm_ldg_stage(sb, Ah, Al, Bh, Bl, K, m0, n0, (kt + 1) * BK, (kt + 1) & 1, tid);
            cp_commit();
            CP_WAIT(1);
        } else {
            CP_WAIT(0);
        }
        __syncthreads();

        const uint32_t st = (kt & 1) * STG_B;
#pragma unroll
        for (int ks = 0; ks < 2; ks++) {
            const uint32_t kh = ks * 16;
            uint32_t ah[2][4], al[2][4];
#pragma unroll
            for (int mt = 0; mt < 2; mt++) {
                uint32_t arow = wm * 32 + mt * 16 + lrow;
                uint32_t ao = st + arow * SKB + (kh + lcol) * 2;
                ldsm_x4(sb + O_AH + ao, ah[mt][0], ah[mt][1], ah[mt][2], ah[mt][3]);
                ldsm_x4(sb + O_AL + ao, al[mt][0], al[mt][1], al[mt][2], al[mt][3]);
            }
#pragma unroll
            for (int ng = 0; ng < 4; ng++) {
                uint32_t brow = wn * 64 + ng * 16 + lrow;
                uint32_t bo = st + brow * SKB + (kh + lcol) * 2;
                uint32_t bh[4], bl[4];
                ldsm_x4(sb + O_BH + bo, bh[0], bh[1], bh[2], bh[3]);
                ldsm_x4(sb + O_BL + bo, bl[0], bl[1], bl[2], bl[3]);
#pragma unroll
                for (int mt = 0; mt < 2; mt++) {
#pragma unroll
                    for (int half = 0; half < 2; half++) {
                        float* cc = acc[mt][ng * 2 + half];
                        uint32_t b0h = half ? bh[1] : bh[0], b1h = half ? bh[3] : bh[2];
                        uint32_t b0l = half ? bl[1] : bl[0], b1l = half ? bl[3] : bl[2];
                        mma16816(cc, ah[mt][0], ah[mt][1], ah[mt][2], ah[mt][3], b0h, b1h);
                        mma16816(cc, ah[mt][0], ah[mt][1], ah[mt][2], ah[mt][3], b0l, b1l);
                        mma16816(cc, al[mt][0], al[mt][1], al[mt][2], al[mt][3], b0h, b1h);
                    }
                }
            }
        }
        __syncthreads();
    }

    const int g = lane >> 2, tg = lane & 3;
#pragma unroll
    for (int mt = 0; mt < 2; mt++) {
#pragma unroll
        for (int nt = 0; nt < 8; nt++) {
            int row = m0 + wm * 32 + mt * 16 + g;
            int col = n0 + wn * 64 + nt * 8 + tg * 2;
            float* cc = acc[mt][nt];
            float2 v0 = make_float2(cc[0], cc[1]);
            float2 v1 = make_float2(cc[2], cc[3]);
            if (ADD) {
                float2 a0 = *(const float2*)(add + (size_t)row * N + col);
                float2 a1 = *(const float2*)(add + (size_t)(row + 8) * N + col);
                v0.x += a0.x;
                v0.y += a0.y;
                v1.x += a1.x;
                v1.y += a1.y;
            }
            *(float2*)(C + (size_t)row * N + col) = v0;
            *(float2*)(C + (size_t)(row + 8) * N + col) = v1;
        }
    }
}

// ===================== RoPE + l2-norm + split (from fused qkv) =====================
__global__ void rope_l2_split_kernel(const float* __restrict__ qkv, const float* __restrict__ cosb,
                                     const float* __restrict__ sinb,
                                     __nv_bfloat16* __restrict__ oh, __nv_bfloat16* __restrict__ ol,
                                     int colOff, int nheads) {
    const int s = blockIdx.x, hh = blockIdx.y, t = threadIdx.x;
    const float* p = qkv + (size_t)s * NQKV + colOff + hh * HDIM;
    float2 xv = *(const float2*)(p + 2 * t);
    float c = cosb[s * (HDIM / 2) + t];
    float sn = sinb[s * (HDIM / 2) + t];
    float o_r = xv.x * c - xv.y * sn;
    float o_i = xv.x * sn + xv.y * c;
    float ss = o_r * o_r + o_i * o_i;
#pragma unroll
    for (int off = 16; off; off >>= 1) ss += __shfl_xor_sync(0xffffffffu, ss, off);
    __shared__ float wsum[2];
    if ((t & 31) == 0) wsum[t >> 5] = ss;
    __syncthreads();
    float r = rsqrtf((wsum[0] + wsum[1]) / (float)HDIM + 1e-5f);
    __nv_bfloat162 h2, l2;
    split2(o_r * r, o_i * r, h2, l2);
    size_t o = (size_t)s * nheads * HDIM + hh * HDIM + 2 * t;
    *(__nv_bfloat162*)(oh + o) = h2;
    *(__nv_bfloat162*)(ol + o) = l2;
}

// ===================== bf16x3 flash attention via mma.sync =====================
// Q tile 128 x KV tile 64, 8 warps (16 q rows each), 256 threads.
#define ASTR 136     // halves per smem row
#define ASTRB 272    // bytes
#define A_QH 0
#define A_QL (128 * ASTRB)
#define A_KV0 (2 * 128 * ASTRB)       // 69632
#define KVBLK (4 * 64 * ASTRB)        // 69632 (KH,KL,VH,VL)
#define KV_KH 0
#define KV_KL (64 * ASTRB)
#define KV_VH (2 * 64 * ASTRB)
#define KV_VL (3 * 64 * ASTRB)
#define ATT_SMEM (A_KV0 + 2 * KVBLK)  // 208896

__device__ __forceinline__ void att_load_kv(uint32_t sb, const __nv_bfloat16* kh,
                                            const __nv_bfloat16* kl, const __nv_bfloat16* vh,
                                            const __nv_bfloat16* vl, int kv0, int kvh, int stage,
                                            int tid) {
    uint32_t base = sb + A_KV0 + stage * KVBLK;
#pragma unroll
    for (int i = 0; i < 4; i++) {
        int id = i * 256 + tid;
        int r = id >> 4, c = id & 15;
        uint32_t so = r * ASTRB + c * 16;
        size_t go = (size_t)(kv0 + r) * (NKVH * HDIM) + kvh * HDIM + c * 8;
        cp_async16(base + KV_KH + so, kh + go);
        cp_async16(base + KV_KL + so, kl + go);
        cp_async16(base + KV_VH + so, vh + go);
        cp_async16(base + KV_VL + so, vl + go);
    }
}

__global__ void __launch_bounds__(256, 1)
    flash_attn_bf16_kernel(const __nv_bfloat16* __restrict__ qh, const __nv_bfloat16* __restrict__ ql,
                           const __nv_bfloat16* __restrict__ kh, const __nv_bfloat16* __restrict__ kl,
                           const __nv_bfloat16* __restrict__ vh, const __nv_bfloat16* __restrict__ vl,
                           __nv_bfloat16* __restrict__ oh, __nv_bfloat16* __restrict__ ol) {
    extern __shared__ char smem[];
    const uint32_t sb = smem_to_u32(smem);
    const int qb = (gridDim.x - 1) - blockIdx.x;  // heavy blocks first
    const int h = blockIdx.y;
    const int kvh = h >> 2;
    const int tid = threadIdx.x, wid = tid >> 5, lane = tid & 31;
    const float scale = 0.08838834764831845f;

    // load Q tile (hi/lo)
#pragma unroll
    for (int i = 0; i < 8; i++) {
        int id = i * 256 + tid;
        int r = id >> 4, c = id & 15;
        uint32_t so = r * ASTRB + c * 16;
        size_t go = (size_t)(qb * 128 + r) * (NHEADS * HDIM) + h * HDIM + c * 8;
        cp_async16(sb + A_QH + so, qh + go);
        cp_async16(sb + A_QL + so, ql + go);
    }
    att_load_kv(sb, kh, kl, vh, vl, 0, kvh, 0, tid);
    cp_commit();

    float oacc[16][4];
#pragma unroll
    for (int f = 0; f < 16; f++)
#pragma unroll
        for (int c = 0; c < 4; c++) oacc[f][c] = 0.f;
    float m0 = -1e30f, m1 = -1e30f, l0 = 0.f, l1 = 0.f;

    const int brow = wid * 16;
    const int qrow_g = qb * 128 + brow;
    const int lr = lane & 15, lc = (lane >> 4) * 8;
    const int lgrp = lane >> 2, lq = lane & 3;

    const int jmax = 2 * qb + 1;
    for (int j = 0; j <= jmax; j++) {
        if (j < jmax) {
            att_load_kv(sb, kh, kl, vh, vl, (j + 1) * 64, kvh, (j + 1) & 1, tid);
            cp_commit();
            CP_WAIT(1);
        } else {
            CP_WAIT(0);
        }
        __syncthreads();
        const uint32_t kvb = sb + A_KV0 + (j & 1) * KVBLK;
        const bool active = (j * 64) <= (qrow_g + 15);
        if (active) {
            // ---- S = Q K^T (bf16x3) ----
            float sacc[8][4];
#pragma unroll
            for (int f = 0; f < 8; f++)
#pragma unroll
                for (int c = 0; c < 4; c++) sacc[f][c] = 0.f;
#pragma unroll
            for (int ks = 0; ks < 8; ks++) {
                uint32_t aoff = (brow + lr) * ASTRB + (ks * 16 + lc) * 2;
                uint32_t a_h[4], a_l[4];
                ldsm_x4(sb + A_QH + aoff, a_h[0], a_h[1], a_h[2], a_h[3]);
                ldsm_x4(sb + A_QL + aoff, a_l[0], a_l[1], a_l[2], a_l[3]);
#pragma unroll
                for (int g = 0; g < 4; g++) {
                    uint32_t boff = (g * 16 + lr) * ASTRB + (ks * 16 + lc) * 2;
                    uint32_t bh_[4], bl_[4];
                    ldsm_x4(kvb + KV_KH + boff, bh_[0], bh_[1], bh_[2], bh_[3]);
                    ldsm_x4(kvb + KV_KL + boff, bl_[0], bl_[1], bl_[2], bl_[3]);
#pragma unroll
                    for (int hv = 0; hv < 2; hv++) {
                        float* cc = sacc[g * 2 + hv];
                        uint32_t b0h = hv ? bh_[1] : bh_[0], b1h = hv ? bh_[3] : bh_[2];
                        uint32_t b0l = hv ? bl_[1] : bl_[0], b1l = hv ? bl_[3] : bl_[2];
                        mma16816(cc, a_h[0], a_h[1], a_h[2], a_h[3], b0h, b1h);
                        mma16816(cc, a_h[0], a_h[1], a_h[2], a_h[3], b0l, b1l);
                        mma16816(cc, a_l[0], a_l[1], a_l[2], a_l[3], b0h, b1h);
                    }
                }
            }
            // ---- mask + scale + online softmax ----
            const int row0 = qrow_g + lgrp, row1 = row0 + 8;
            float mx0 = -1e30f, mx1 = -1e30f;
#pragma unroll
            for (int nb = 0; nb < 8; nb++) {
                int col = j * 64 + nb * 8 + 2 * lq;
                float* cc = sacc[nb];
                cc[0] = cc[0] * scale + (col <= row0 ? 0.f : -1e9f);
                cc[1] = cc[1] * scale + (col + 1 <= row0 ? 0.f : -1e9f);
                cc[2] = cc[2] * scale + (col <= row1 ? 0.f : -1e9f);
                cc[3] = cc[3] * scale + (col + 1 <= row1 ? 0.f : -1e9f);
                mx0 = fmaxf(mx0, fmaxf(cc[0], cc[1]));
                mx1 = fmaxf(mx1, fmaxf(cc[2], cc[3]));
            }
            mx0 = fmaxf(mx0, __shfl_xor_sync(0xffffffffu, mx0, 1));
            mx0 = fmaxf(mx0, __shfl_xor_sync(0xffffffffu, mx0, 2));
            mx1 = fmaxf(mx1, __shfl_xor_sync(0xffffffffu, mx1, 1));
            mx1 = fmaxf(mx1, __shfl_xor_sync(0xffffffffu, mx1, 2));
            float mn0 = fmaxf(m0, mx0), mn1 = fmaxf(m1, mx1);
            float corr0 = __expf(m0 - mn0), corr1 = __expf(m1 - mn1);
            m0 = mn0;
            m1 = mn1;
            float s0 = 0.f, s1 = 0.f;
#pragma unroll
            for (int nb = 0; nb < 8; nb++) {
                float* cc = sacc[nb];
                cc[0] = __expf(cc[0] - mn0);
                cc[1] = __expf(cc[1] - mn0);
                cc[2] = __expf(cc[2] - mn1);
                cc[3] = __expf(cc[3] - mn1);
                s0 += cc[0] + cc[1];
                s1 += cc[2] + cc[3];
            }
            s0 += __shfl_xor_sync(0xffffffffu, s0, 1);
            s0 += __shfl_xor_sync(0xffffffffu, s0, 2);
            s1 += __shfl_xor_sync(0xffffffffu, s1, 1);
            s1 += __shfl_xor_sync(0xffffffffu, s1, 2);
            l0 = l0 * corr0 + s0;
            l1 = l1 * corr1 + s1;
#pragma unroll
            for (int f = 0; f < 16; f++) {
                oacc[f][0] *= corr0;
                oacc[f][1] *= corr0;
                oacc[f][2] *= corr1;
                oacc[f][3] *= corr1;
            }
            // ---- O += P V (bf16x3) ----
#pragma unroll
            for (int g2 = 0; g2 < 4; g2++) {
                float* p0 = sacc[2 * g2];
                float* p1 = sacc[2 * g2 + 1];
                uint32_t aph[4], apl[4];
                pack2(p0[0], p0[1], aph[0], apl[0]);
                pack2(p0[2], p0[3], aph[1], apl[1]);
                pack2(p1[0], p1[1], aph[2], apl[2]);
                pack2(p1[2], p1[3], aph[3], apl[3]);
#pragma unroll
                for (int gd = 0; gd < 8; gd++) {
                    uint32_t voff = (g2 * 16 + lr) * ASTRB + (gd * 16 + lc) * 2;
                    uint32_t vh_[4], vl_[4];
                    ldsm_x4_t(kvb + KV_VH + voff, vh_[0], vh_[1], vh_[2], vh_[3]);
                    ldsm_x4_t(kvb + KV_VL + voff, vl_[0], vl_[1], vl_[2], vl_[3]);
                    float* o0 = oacc[2 * gd];
                    float* o1 = oacc[2 * gd + 1];
                    mma16816(o0, aph[0], aph[1], aph[2], aph[3], vh_[0], vh_[1]);
                    mma16816(o0, aph[0], aph[1], aph[2], aph[3], vl_[0], vl_[1]);
                    mma16816(o0, apl[0], apl[1], apl[2], apl[3], vh_[0], vh_[1]);
                    mma16816(o1, aph[0], aph[1], aph[2], aph[3], vh_[2], vh_[3]);
                    mma16816(o1, aph[0], aph[1], aph[2], aph[3], vl_[2], vl_[3]);
                    mma16816(o1, apl[0], apl[1], apl[2], apl[3], vh_[2], vh_[3]);
                }
            }
        }
        __syncthreads();
    }

    // epilogue: O /= l, write hi/lo bf16
    float li0 = 1.f / l0, li1 = 1.f / l1;
    const int orow0 = qrow_g + lgrp;
#pragma unroll
    for (int nt = 0; nt < 16; nt++) {
        float v0 = oacc[nt][0] * li0, v1 = oacc[nt][1] * li0;
        float v2 = oacc[nt][2] * li1, v3 = oacc[nt][3] * li1;
        int col = h * HDIM + nt * 8 + 2 * lq;
        __nv_bfloat162 h2, l2;
        split2(v0, v1, h2, l2);
        *(__nv_bfloat162*)(oh + (size_t)orow0 * DMODEL + col) = h2;
        *(__nv_bfloat162*)(ol + (size_t)orow0 * DMODEL + col) = l2;
        split2(v2, v3, h2, l2);
        *(__nv_bfloat162*)(oh + (size_t)(orow0 + 8) * DMODEL + col) = h2;
        *(__nv_bfloat162*)(ol + (size_t)(orow0 + 8) * DMODEL + col) = l2;
    }
}

// ===================== launch =====================
extern "C" void kernel_launch(void* const* d_in, const int* in_sizes, int n_in,
                              void* d_out, int out_size) {
    const float* hidden = (const float*)d_in[0];
    const float* fcos = (const float*)d_in[2];
    const float* fsin = (const float*)d_in[3];
    const float* ln1 = (const float*)d_in[4];
    const float* wq = (const float*)d_in[5];
    const float* wk = (const float*)d_in[6];
    const float* wv = (const float*)d_in[7];
    const float* wo = (const float*)d_in[8];
    const float* ln2 = (const float*)d_in[9];
    const float* gate_w = (const float*)d_in[10];
    const float* up_w = (const float*)d_in[11];
    const float* down_w = (const float*)d_in[12];
    float* out = (float*)d_out;

    float *qkv, *hbuf, *gu;
    cudaGetSymbolAddress((void**)&qkv, g_qkv);
    cudaGetSymbolAddress((void**)&hbuf, g_h);
    cudaGetSymbolAddress((void**)&gu, g_gu);
    __nv_bfloat16 *xnh, *xnl, *qh, *ql, *kkh, *kkl, *vvh, *vvl, *attnh, *attnl, *x2h, *x2l, *ffh,
        *ffl;
    cudaGetSymbolAddress((void**)&xnh, g_xnh);
    cudaGetSymbolAddress((void**)&xnl, g_xnl);
    cudaGetSymbolAddress((void**)&qh, g_qh);
    cudaGetSymbolAddress((void**)&ql, g_ql);
    cudaGetSymbolAddress((void**)&kkh, g_kh);
    cudaGetSymbolAddress((void**)&kkl, g_kl);
    cudaGetSymbolAddress((void**)&vvh, g_vh);
    cudaGetSymbolAddress((void**)&vvl, g_vl);
    cudaGetSymbolAddress((void**)&attnh, g_attnh);
    cudaGetSymbolAddress((void**)&attnl, g_attnl);
    cudaGetSymbolAddress((void**)&x2h, g_x2h);
    cudaGetSymbolAddress((void**)&x2l, g_x2l);
    cudaGetSymbolAddress((void**)&ffh, g_ffh);
    cudaGetSymbolAddress((void**)&ffl, g_ffl);
    __nv_bfloat16 *wqkvth, *wqkvtl, *woth, *wotl, *guth, *gutl, *dth, *dtl;
    cudaGetSymbolAddress((void**)&wqkvth, g_wqkvth);
    cudaGetSymbolAddress((void**)&wqkvtl, g_wqkvtl);
    cudaGetSymbolAddress((void**)&woth, g_woth);
    cudaGetSymbolAddress((void**)&wotl, g_wotl);
    cudaGetSymbolAddress((void**)&guth, g_guth);
    cudaGetSymbolAddress((void**)&gutl, g_gutl);
    cudaGetSymbolAddress((void**)&dth, g_dth);
    cudaGetSymbolAddress((void**)&dtl, g_dtl);

    cudaFuncSetAttribute(gemm_bf16x3_kernel<0>, cudaFuncAttributeMaxDynamicSharedMemorySize,
                         GEMM_SMEM);
    cudaFuncSetAttribute(gemm_bf16x3_kernel<1>, cudaFuncAttributeMaxDynamicSharedMemorySize,
                         GEMM_SMEM);
    cudaFuncSetAttribute(flash_attn_bf16_kernel, cudaFuncAttributeMaxDynamicSharedMemorySize,
                         ATT_SMEM);

    dim3 tb(32, 8);
    // weight transpose + split (into fused buffers)
    transpose_split_kernel<<<dim3(DMODEL / 32, DMODEL / 32), tb>>>(wq, wqkvth, wqkvtl, DMODEL,
                                                                   DMODEL);
    transpose_split_kernel<<<dim3((NKVH * HDIM) / 32, DMODEL / 32), tb>>>(
        wk, wqkvth + (size_t)DMODEL * DMODEL, wqkvtl + (size_t)DMODEL * DMODEL, DMODEL,
        NKVH * HDIM);
    transpose_split_kernel<<<dim3((NKVH * HDIM) / 32, DMODEL / 32), tb>>>(
        wv, wqkvth + (size_t)(DMODEL + NKVH * HDIM) * DMODEL,
        wqkvtl + (size_t)(DMODEL + NKVH * HDIM) * DMODEL, DMODEL, NKVH * HDIM);
    transpose_split_kernel<<<dim3(DMODEL / 32, DMODEL / 32), tb>>>(wo, woth, wotl, DMODEL, DMODEL);
    transpose_split_kernel<<<dim3(DFF / 32, DMODEL / 32), tb>>>(gate_w, guth, gutl, DMODEL, DFF);
    transpose_split_kernel<<<dim3(DFF / 32, DMODEL / 32), tb>>>(
        up_w, guth + (size_t)DFF * DMODEL, gutl + (size_t)DFF * DMODEL, DMODEL, DFF);
    transpose_split_kernel<<<dim3(DMODEL / 32, DFF / 32), tb>>>(down_w, dth, dtl, DFF, DMODEL);

    // rmsnorm1 + split
    rmsnorm_split_kernel<<<SEQ, 256>>>(hidden, ln1, xnh, xnl);
    // fused QKV GEMM
    gemm_bf16x3_kernel<0><<<dim3(NQKV / BN, SEQ / BM), 256, GEMM_SMEM>>>(
        xnh, xnl, wqkvth, wqkvtl, qkv, qkv, SEQ, NQKV, DMODEL);
    // RoPE + l2norm + split (q, k), v split
    rope_l2_split_kernel<<<dim3(SEQ, NHEADS), 64>>>(qkv, fcos, fsin, qh, ql, 0, NHEADS);
    rope_l2_split_kernel<<<dim3(SEQ, NKVH), 64>>>(qkv, fcos, fsin, kkh, kkl, DMODEL, NKVH);
    vsplit_kernel<<<SEQ * 256 / 256, 256>>>(qkv, vvh, vvl);
    // attention
    flash_attn_bf16_kernel<<<dim3(SEQ / 128, NHEADS), 256, ATT_SMEM>>>(qh, ql, kkh, kkl, vvh, vvl,
                                                                       attnh, attnl);
    // O proj + residual
    gemm_bf16x3_kernel<1><<<dim3(DMODEL / BN, SEQ / BM), 256, GEMM_SMEM>>>(
        attnh, attnl, woth, wotl, hbuf, hidden, SEQ, DMODEL, DMODEL);
    // rmsnorm2 + split
    rmsnorm_split_kernel<<<SEQ, 256>>>(hbuf, ln2, x2h, x2l);
    // fused gate+up GEMM
    gemm_bf16x3_kernel<0><<<dim3(NGU / BN, SEQ / BM), 256, GEMM_SMEM>>>(
        x2h, x2l, guth, gutl, gu, gu, SEQ, NGU, DMODEL);
    // silu*up + split
    silu_mul_split_kernel<<<4096, 256>>>(gu, ffh, ffl);
    // down + residual
    gemm_bf16x3_kernel<1><<<dim3(DMODEL / BN, SEQ / BM), 256, GEMM_SMEM>>>(
        ffh, ffl, dth, dtl, out, hbuf, SEQ, DMODEL, DFF);
}

// round 5
// speedup vs baseline: 2.6259x; 1.1024x over previous
#include <cuda_runtime.h>
#include <cuda_bf16.h>
#include <cstdint>
#include <math.h>

#define SEQ 2048
#define DMODEL 4096
#define NHEADS 32
#define NKVH 8
#define HDIM 128
#define DFF 16384
#define NQKV 6144   // 4096 q + 1024 k + 1024 v
#define NGU 32768   // 16384 gate + 16384 up

// ===================== scratch =====================
__device__ float g_qkv[SEQ * NQKV];
__device__ float g_h[SEQ * DMODEL];
__device__ float g_gu[SEQ * NGU];

__device__ __nv_bfloat16 g_xnh[SEQ * DMODEL], g_xnl[SEQ * DMODEL];
__device__ __nv_bfloat16 g_qh[SEQ * NHEADS * HDIM], g_ql[SEQ * NHEADS * HDIM];
__device__ __nv_bfloat16 g_kh[SEQ * NKVH * HDIM], g_kl[SEQ * NKVH * HDIM];
__device__ __nv_bfloat16 g_vh[SEQ * NKVH * HDIM], g_vl[SEQ * NKVH * HDIM];
__device__ __nv_bfloat16 g_attnh[SEQ * DMODEL], g_attnl[SEQ * DMODEL];
__device__ __nv_bfloat16 g_x2h[SEQ * DMODEL], g_x2l[SEQ * DMODEL];
__device__ __nv_bfloat16 g_ffh[SEQ * DFF], g_ffl[SEQ * DFF];

__device__ __nv_bfloat16 g_wqkvth[NQKV * DMODEL], g_wqkvtl[NQKV * DMODEL];
__device__ __nv_bfloat16 g_woth[DMODEL * DMODEL], g_wotl[DMODEL * DMODEL];
__device__ __nv_bfloat16 g_guth[(size_t)NGU * DMODEL], g_gutl[(size_t)NGU * DMODEL];
__device__ __nv_bfloat16 g_dth[(size_t)DMODEL * DFF], g_dtl[(size_t)DMODEL * DFF];

// ===================== helpers =====================
__device__ __forceinline__ uint32_t smem_to_u32(const void* p) {
    uint32_t a;
    asm("{ .reg .u64 t; cvta.to.shared.u64 t, %1; cvt.u32.u64 %0, t; }" : "=r"(a) : "l"(p));
    return a;
}
__device__ __forceinline__ void cp_async16(uint32_t saddr, const void* gaddr) {
    asm volatile("cp.async.cg.shared.global [%0], [%1], 16;" ::"r"(saddr), "l"(gaddr));
}
__device__ __forceinline__ void cp_commit() { asm volatile("cp.async.commit_group;" ::: "memory"); }
#define CP_WAIT(N) asm volatile("cp.async.wait_group %0;" ::"n"(N) : "memory")

__device__ __forceinline__ void ldsm_x4(uint32_t addr, uint32_t& r0, uint32_t& r1, uint32_t& r2,
                                        uint32_t& r3) {
    asm volatile("ldmatrix.sync.aligned.m8n8.x4.shared.b16 {%0,%1,%2,%3}, [%4];"
                 : "=r"(r0), "=r"(r1), "=r"(r2), "=r"(r3)
                 : "r"(addr));
}
__device__ __forceinline__ void ldsm_x4_t(uint32_t addr, uint32_t& r0, uint32_t& r1, uint32_t& r2,
                                          uint32_t& r3) {
    asm volatile("ldmatrix.sync.aligned.m8n8.x4.trans.shared.b16 {%0,%1,%2,%3}, [%4];"
                 : "=r"(r0), "=r"(r1), "=r"(r2), "=r"(r3)
                 : "r"(addr));
}
__device__ __forceinline__ void mma16816(float* c, uint32_t a0, uint32_t a1, uint32_t a2,
                                         uint32_t a3, uint32_t b0, uint32_t b1) {
    asm volatile(
        "mma.sync.aligned.m16n8k16.row.col.f32.bf16.bf16.f32 "
        "{%0,%1,%2,%3}, {%4,%5,%6,%7}, {%8,%9}, {%0,%1,%2,%3};"
        : "+f"(c[0]), "+f"(c[1]), "+f"(c[2]), "+f"(c[3])
        : "r"(a0), "r"(a1), "r"(a2), "r"(a3), "r"(b0), "r"(b1));
}

__device__ __forceinline__ void split2(float a, float b, __nv_bfloat162& h2, __nv_bfloat162& l2) {
    __nv_bfloat16 ha = __float2bfloat16(a), hb = __float2bfloat16(b);
    __nv_bfloat16 la = __float2bfloat16(a - __bfloat162float(ha));
    __nv_bfloat16 lb = __float2bfloat16(b - __bfloat162float(hb));
    h2 = __halves2bfloat162(ha, hb);
    l2 = __halves2bfloat162(la, lb);
}
__device__ __forceinline__ void pack2(float x, float y, uint32_t& hi, uint32_t& lo) {
    __nv_bfloat162 h2, l2;
    split2(x, y, h2, l2);
    hi = *(uint32_t*)&h2;
    lo = *(uint32_t*)&l2;
}

// ===================== RMSNorm + split =====================
__global__ void rmsnorm_split_kernel(const float* __restrict__ x, const float* __restrict__ w,
                                     __nv_bfloat16* __restrict__ yh,
                                     __nv_bfloat16* __restrict__ yl) {
    const int row = blockIdx.x;
    const float* xr = x + (size_t)row * DMODEL;
    float ss = 0.f;
#pragma unroll
    for (int i = 0; i < DMODEL / 1024; i++) {
        int idx = i * 1024 + threadIdx.x * 4;
        float4 v = *(const float4*)(xr + idx);
        ss += v.x * v.x + v.y * v.y + v.z * v.z + v.w * v.w;
    }
#pragma unroll
    for (int off = 16; off; off >>= 1) ss += __shfl_xor_sync(0xffffffffu, ss, off);
    __shared__ float red[8];
    __shared__ float s_scale;
    if ((threadIdx.x & 31) == 0) red[threadIdx.x >> 5] = ss;
    __syncthreads();
    if (threadIdx.x == 0) {
        float tot = 0.f;
#pragma unroll
        for (int i = 0; i < 8; i++) tot += red[i];
        s_scale = rsqrtf(tot / (float)DMODEL + 1e-5f);
    }
    __syncthreads();
    float sc = s_scale;
#pragma unroll
    for (int i = 0; i < DMODEL / 1024; i++) {
        int idx = i * 1024 + threadIdx.x * 4;
        float4 v = *(const float4*)(xr + idx);
        float4 wv = *(const float4*)(w + idx);
        v.x *= sc * wv.x;
        v.y *= sc * wv.y;
        v.z *= sc * wv.z;
        v.w *= sc * wv.w;
        __nv_bfloat162 h0, l0, h1, l1;
        split2(v.x, v.y, h0, l0);
        split2(v.z, v.w, h1, l1);
        __nv_bfloat162* ph = (__nv_bfloat162*)(yh + (size_t)row * DMODEL + idx);
        __nv_bfloat162* pl = (__nv_bfloat162*)(yl + (size_t)row * DMODEL + idx);
        ph[0] = h0;
        ph[1] = h1;
        pl[0] = l0;
        pl[1] = l1;
    }
}

// ===================== V split =====================
__global__ void vsplit_kernel(const float* __restrict__ qkv, __nv_bfloat16* __restrict__ vh,
                              __nv_bfloat16* __restrict__ vl) {
    int i = blockIdx.x * blockDim.x + threadIdx.x;
    int s = i >> 8;
    int c = (i & 255) * 4;
    float4 v = *(const float4*)(qkv + (size_t)s * NQKV + 5120 + c);
    __nv_bfloat162 h0, l0, h1, l1;
    split2(v.x, v.y, h0, l0);
    split2(v.z, v.w, h1, l1);
    size_t o = (size_t)s * 1024 + c;
    *(__nv_bfloat162*)(vh + o) = h0;
    *(__nv_bfloat162*)(vh + o + 2) = h1;
    *(__nv_bfloat162*)(vl + o) = l0;
    *(__nv_bfloat162*)(vl + o + 2) = l1;
}

// ===================== silu(gate)*up + split =====================
__global__ void silu_mul_split_kernel(const float* __restrict__ gu, __nv_bfloat16* __restrict__ h,
                                      __nv_bfloat16* __restrict__ l) {
    const long long n4 = (long long)SEQ * DFF / 4;
    for (long long i = (long long)blockIdx.x * blockDim.x + threadIdx.x; i < n4;
         i += (long long)gridDim.x * blockDim.x) {
        int s = (int)(i / (DFF / 4));
        int c = (int)(i % (DFF / 4)) * 4;
        float4 gv = *(const float4*)(gu + (size_t)s * NGU + c);
        float4 uv = *(const float4*)(gu + (size_t)s * NGU + DFF + c);
        gv.x = gv.x / (1.f + expf(-gv.x)) * uv.x;
        gv.y = gv.y / (1.f + expf(-gv.y)) * uv.y;
        gv.z = gv.z / (1.f + expf(-gv.z)) * uv.z;
        gv.w = gv.w / (1.f + expf(-gv.w)) * uv.w;
        __nv_bfloat162 h0, l0, h1, l1;
        split2(gv.x, gv.y, h0, l0);
        split2(gv.z, gv.w, h1, l1);
        size_t o = (size_t)s * DFF + c;
        *(__nv_bfloat162*)(h + o) = h0;
        *(__nv_bfloat162*)(h + o + 2) = h1;
        *(__nv_bfloat162*)(l + o) = l0;
        *(__nv_bfloat162*)(l + o + 2) = l1;
    }
}

// ===================== transpose + split =====================
__global__ void transpose_split_kernel(const float* __restrict__ B, __nv_bfloat16* __restrict__ Th,
                                       __nv_bfloat16* __restrict__ Tl, int Kdim, int Ndim) {
    __shared__ float t[32][33];
    const int n0 = blockIdx.x * 32, k0 = blockIdx.y * 32;
    const int tx = threadIdx.x, ty = threadIdx.y;
#pragma unroll
    for (int i = 0; i < 32; i += 8) t[ty + i][tx] = B[(size_t)(k0 + ty + i) * Ndim + n0 + tx];
    __syncthreads();
#pragma unroll
    for (int i = 0; i < 32; i += 8) {
        float v = t[tx][ty + i];
        __nv_bfloat16 hv = __float2bfloat16(v);
        __nv_bfloat16 lv = __float2bfloat16(v - __bfloat162float(hv));
        size_t o = (size_t)(n0 + ty + i) * Kdim + k0 + tx;
        Th[o] = hv;
        Tl[o] = lv;
    }
}

// ===================== bf16x3 GEMM via mma.sync =====================
// CTA tile 128x256, warp tile 64x64 (8 warps 2x4), BK=32, 3-stage cp.async.
#define BM 128
#define BN 256
#define BK 32
#define SKB 80                      // bytes per smem row (32 halves + pad)
#define STG_A (BM * SKB)            // 10240
#define STG_BB (BN * SKB)           // 20480
#define SO_AH 0
#define SO_AL STG_A
#define SO_BH (2 * STG_A)
#define SO_BL (2 * STG_A + STG_BB)
#define STG_TOT (2 * STG_A + 2 * STG_BB)  // 61440
#define NSTAGE 3
#define GEMM_SMEM (NSTAGE * STG_TOT)      // 184320

__device__ __forceinline__ void gemm_ldg_stage(uint32_t sb, const __nv_bfloat16* Ah,
                                               const __nv_bfloat16* Al, const __nv_bfloat16* Bh,
                                               const __nv_bfloat16* Bl, int K, int m0, int n0,
                                               int k0, int stage, int tid) {
    const uint32_t base = sb + stage * STG_TOT;
#pragma unroll
    for (int i = 0; i < 2; i++) {
        int id = i * 256 + tid;
        int r = id >> 2, c = id & 3;
        uint32_t sa = r * SKB + c * 16;
        size_t ga = (size_t)(m0 + r) * K + k0 + c * 8;
        cp_async16(base + SO_AH + sa, Ah + ga);
        cp_async16(base + SO_AL + sa, Al + ga);
    }
#pragma unroll
    for (int i = 0; i < 4; i++) {
        int id = i * 256 + tid;
        int r = id >> 2, c = id & 3;
        uint32_t sa = r * SKB + c * 16;
        size_t gb = (size_t)(n0 + r) * K + k0 + c * 8;
        cp_async16(base + SO_BH + sa, Bh + gb);
        cp_async16(base + SO_BL + sa, Bl + gb);
    }
}

template <int ADD>
__global__ void __launch_bounds__(256, 1)
    gemm_bf16x3_kernel(const __nv_bfloat16* __restrict__ Ah, const __nv_bfloat16* __restrict__ Al,
                       const __nv_bfloat16* __restrict__ Bh, const __nv_bfloat16* __restrict__ Bl,
                       float* __restrict__ C, const float* __restrict__ add, int M, int N, int K) {
    extern __shared__ char smem[];
    const uint32_t sb = smem_to_u32(smem);
    const int tid = threadIdx.x;
    const int wid = tid >> 5, lane = tid & 31;
    const int wm = wid >> 2, wn = wid & 3;  // 2 x 4 warp grid
    const int m0 = blockIdx.y * BM, n0 = blockIdx.x * BN;

    float acc[4][8][4];
#pragma unroll
    for (int a = 0; a < 4; a++)
#pragma unroll
        for (int b = 0; b < 8; b++)
#pragma unroll
            for (int c = 0; c < 4; c++) acc[a][b][c] = 0.f;

    const int nk = K / BK;
    gemm_ldg_stage(sb, Ah, Al, Bh, Bl, K, m0, n0, 0, 0, tid);
    cp_commit();
    gemm_ldg_stage(sb, Ah, Al, Bh, Bl, K, m0, n0, BK, 1, tid);
    cp_commit();

    const int lr = lane & 15;
    const int lc = (lane >> 4) * 8;

    int stage = 0;
    for (int kt = 0; kt < nk; kt++) {
        if (kt + 1 < nk) {
            CP_WAIT(1);
        } else {
            CP_WAIT(0);
        }
        __syncthreads();

        const uint32_t stb = sb + stage * STG_TOT;
#pragma unroll
        for (int ks = 0; ks < 2; ks++) {
            const uint32_t kb = (ks * 16 + lc) * 2;
            uint32_t ah[4][4], al[4][4];
#pragma unroll
            for (int mt = 0; mt < 4; mt++) {
                uint32_t arow = wm * 64 + mt * 16 + lr;
                uint32_t ao = stb + arow * SKB + kb;
                ldsm_x4(ao + SO_AH, ah[mt][0], ah[mt][1], ah[mt][2], ah[mt][3]);
                ldsm_x4(ao + SO_AL, al[mt][0], al[mt][1], al[mt][2], al[mt][3]);
            }
#pragma unroll
            for (int ng = 0; ng < 4; ng++) {
                uint32_t brow = wn * 64 + ng * 16 + lr;
                uint32_t bo = stb + brow * SKB + kb;
                uint32_t bh[4], bl[4];
                ldsm_x4(bo + SO_BH, bh[0], bh[1], bh[2], bh[3]);
                ldsm_x4(bo + SO_BL, bl[0], bl[1], bl[2], bl[3]);
#pragma unroll
                for (int mt = 0; mt < 4; mt++) {
#pragma unroll
                    for (int half = 0; half < 2; half++) {
                        float* cc = acc[mt][ng * 2 + half];
                        uint32_t b0h = half ? bh[1] : bh[0], b1h = half ? bh[3] : bh[2];
                        uint32_t b0l = half ? bl[1] : bl[0], b1l = half ? bl[3] : bl[2];
                        mma16816(cc, ah[mt][0], ah[mt][1], ah[mt][2], ah[mt][3], b0h, b1h);
                        mma16816(cc, ah[mt][0], ah[mt][1], ah[mt][2], ah[mt][3], b0l, b1l);
                        mma16816(cc, al[mt][0], al[mt][1], al[mt][2], al[mt][3], b0h, b1h);
                    }
                }
            }
        }
        if (kt + 2 < nk) {
            gemm_ldg_stage(sb, Ah, Al, Bh, Bl, K, m0, n0, (kt + 2) * BK, (kt + 2) % NSTAGE, tid);
            cp_commit();
        }
        stage = (stage + 1) % NSTAGE;
        __syncthreads();
    }

    const int g = lane >> 2, tg = lane & 3;
#pragma unroll
    for (int mt = 0; mt < 4; mt++) {
#pragma unroll
        for (int nt = 0; nt < 8; nt++) {
            int row = m0 + wm * 64 + mt * 16 + g;
            int col = n0 + wn * 64 + nt * 8 + tg * 2;
            float* cc = acc[mt][nt];
            float2 v0 = make_float2(cc[0], cc[1]);
            float2 v1 = make_float2(cc[2], cc[3]);
            if (ADD) {
                float2 a0 = *(const float2*)(add + (size_t)row * N + col);
                float2 a1 = *(const float2*)(add + (size_t)(row + 8) * N + col);
                v0.x += a0.x;
                v0.y += a0.y;
                v1.x += a1.x;
                v1.y += a1.y;
            }
            *(float2*)(C + (size_t)row * N + col) = v0;
            *(float2*)(C + (size_t)(row + 8) * N + col) = v1;
        }
    }
}

// ===================== RoPE + l2-norm + split =====================
__global__ void rope_l2_split_kernel(const float* __restrict__ qkv, const float* __restrict__ cosb,
                                     const float* __restrict__ sinb,
                                     __nv_bfloat16* __restrict__ oh, __nv_bfloat16* __restrict__ ol,
                                     int colOff, int nheads) {
    const int s = blockIdx.x, hh = blockIdx.y, t = threadIdx.x;
    const float* p = qkv + (size_t)s * NQKV + colOff + hh * HDIM;
    float2 xv = *(const float2*)(p + 2 * t);
    float c = cosb[s * (HDIM / 2) + t];
    float sn = sinb[s * (HDIM / 2) + t];
    float o_r = xv.x * c - xv.y * sn;
    float o_i = xv.x * sn + xv.y * c;
    float ss = o_r * o_r + o_i * o_i;
#pragma unroll
    for (int off = 16; off; off >>= 1) ss += __shfl_xor_sync(0xffffffffu, ss, off);
    __shared__ float wsum[2];
    if ((t & 31) == 0) wsum[t >> 5] = ss;
    __syncthreads();
    float r = rsqrtf((wsum[0] + wsum[1]) / (float)HDIM + 1e-5f);
    __nv_bfloat162 h2, l2;
    split2(o_r * r, o_i * r, h2, l2);
    size_t o = (size_t)s * nheads * HDIM + hh * HDIM + 2 * t;
    *(__nv_bfloat162*)(oh + o) = h2;
    *(__nv_bfloat162*)(ol + o) = l2;
}

// ===================== bf16x3 flash attention via mma.sync =====================
#define ASTRB 272
#define A_QH 0
#define A_QL (128 * ASTRB)
#define A_KV0 (2 * 128 * ASTRB)
#define KVBLK (4 * 64 * ASTRB)
#define KV_KH 0
#define KV_KL (64 * ASTRB)
#define KV_VH (2 * 64 * ASTRB)
#define KV_VL (3 * 64 * ASTRB)
#define ATT_SMEM (A_KV0 + 2 * KVBLK)

__device__ __forceinline__ void att_load_kv(uint32_t sb, const __nv_bfloat16* kh,
                                            const __nv_bfloat16* kl, const __nv_bfloat16* vh,
                                            const __nv_bfloat16* vl, int kv0, int kvh, int stage,
                                            int tid) {
    uint32_t base = sb + A_KV0 + stage * KVBLK;
#pragma unroll
    for (int i = 0; i < 4; i++) {
        int id = i * 256 + tid;
        int r = id >> 4, c = id & 15;
        uint32_t so = r * ASTRB + c * 16;
        size_t go = (size_t)(kv0 + r) * (NKVH * HDIM) + kvh * HDIM + c * 8;
        cp_async16(base + KV_KH + so, kh + go);
        cp_async16(base + KV_KL + so, kl + go);
        cp_async16(base + KV_VH + so, vh + go);
        cp_async16(base + KV_VL + so, vl + go);
    }
}

__global__ void __launch_bounds__(256, 1)
    flash_attn_bf16_kernel(const __nv_bfloat16* __restrict__ qh, const __nv_bfloat16* __restrict__ ql,
                           const __nv_bfloat16* __restrict__ kh, const __nv_bfloat16* __restrict__ kl,
                           const __nv_bfloat16* __restrict__ vh, const __nv_bfloat16* __restrict__ vl,
                           __nv_bfloat16* __restrict__ oh, __nv_bfloat16* __restrict__ ol) {
    extern __shared__ char smem[];
    const uint32_t sb = smem_to_u32(smem);
    const int qb = (gridDim.x - 1) - blockIdx.x;
    const int h = blockIdx.y;
    const int kvh = h >> 2;
    const int tid = threadIdx.x, wid = tid >> 5, lane = tid & 31;
    const float scale = 0.08838834764831845f;

#pragma unroll
    for (int i = 0; i < 8; i++) {
        int id = i * 256 + tid;
        int r = id >> 4, c = id & 15;
        uint32_t so = r * ASTRB + c * 16;
        size_t go = (size_t)(qb * 128 + r) * (NHEADS * HDIM) + h * HDIM + c * 8;
        cp_async16(sb + A_QH + so, qh + go);
        cp_async16(sb + A_QL + so, ql + go);
    }
    att_load_kv(sb, kh, kl, vh, vl, 0, kvh, 0, tid);
    cp_commit();

    float oacc[16][4];
#pragma unroll
    for (int f = 0; f < 16; f++)
#pragma unroll
        for (int c = 0; c < 4; c++) oacc[f][c] = 0.f;
    float m0 = -1e30f, m1 = -1e30f, l0 = 0.f, l1 = 0.f;

    const int brow = wid * 16;
    const int qrow_g = qb * 128 + brow;
    const int lr = lane & 15, lc = (lane >> 4) * 8;
    const int lgrp = lane >> 2, lq = lane & 3;

    const int jmax = 2 * qb + 1;
    for (int j = 0; j <= jmax; j++) {
        if (j < jmax) {
            att_load_kv(sb, kh, kl, vh, vl, (j + 1) * 64, kvh, (j + 1) & 1, tid);
            cp_commit();
            CP_WAIT(1);
        } else {
            CP_WAIT(0);
        }
        __syncthreads();
        const uint32_t kvb = sb + A_KV0 + (j & 1) * KVBLK;
        const bool active = (j * 64) <= (qrow_g + 15);
        if (active) {
            float sacc[8][4];
#pragma unroll
            for (int f = 0; f < 8; f++)
#pragma unroll
                for (int c = 0; c < 4; c++) sacc[f][c] = 0.f;
#pragma unroll
            for (int ks = 0; ks < 8; ks++) {
                uint32_t aoff = (brow + lr) * ASTRB + (ks * 16 + lc) * 2;
                uint32_t a_h[4], a_l[4];
                ldsm_x4(sb + A_QH + aoff, a_h[0], a_h[1], a_h[2], a_h[3]);
                ldsm_x4(sb + A_QL + aoff, a_l[0], a_l[1], a_l[2], a_l[3]);
#pragma unroll
                for (int g = 0; g < 4; g++) {
                    uint32_t boff = (g * 16 + lr) * ASTRB + (ks * 16 + lc) * 2;
                    uint32_t bh_[4], bl_[4];
                    ldsm_x4(kvb + KV_KH + boff, bh_[0], bh_[1], bh_[2], bh_[3]);
                    ldsm_x4(kvb + KV_KL + boff, bl_[0], bl_[1], bl_[2], bl_[3]);
#pragma unroll
                    for (int hv = 0; hv < 2; hv++) {
                        float* cc = sacc[g * 2 + hv];
                        uint32_t b0h = hv ? bh_[1] : bh_[0], b1h = hv ? bh_[3] : bh_[2];
                        uint32_t b0l = hv ? bl_[1] : bl_[0], b1l = hv ? bl_[3] : bl_[2];
                        mma16816(cc, a_h[0], a_h[1], a_h[2], a_h[3], b0h, b1h);
                        mma16816(cc, a_h[0], a_h[1], a_h[2], a_h[3], b0l, b1l);
                        mma16816(cc, a_l[0], a_l[1], a_l[2], a_l[3], b0h, b1h);
                    }
                }
            }
            const int row0 = qrow_g + lgrp, row1 = row0 + 8;
            float mx0 = -1e30f, mx1 = -1e30f;
#pragma unroll
            for (int nb = 0; nb < 8; nb++) {
                int col = j * 64 + nb * 8 + 2 * lq;
                float* cc = sacc[nb];
                cc[0] = cc[0] * scale + (col <= row0 ? 0.f : -1e9f);
                cc[1] = cc[1] * scale + (col + 1 <= row0 ? 0.f : -1e9f);
                cc[2] = cc[2] * scale + (col <= row1 ? 0.f : -1e9f);
                cc[3] = cc[3] * scale + (col + 1 <= row1 ? 0.f : -1e9f);
                mx0 = fmaxf(mx0, fmaxf(cc[0], cc[1]));
                mx1 = fmaxf(mx1, fmaxf(cc[2], cc[3]));
            }
            mx0 = fmaxf(mx0, __shfl_xor_sync(0xffffffffu, mx0, 1));
            mx0 = fmaxf(mx0, __shfl_xor_sync(0xffffffffu, mx0, 2));
            mx1 = fmaxf(mx1, __shfl_xor_sync(0xffffffffu, mx1, 1));
            mx1 = fmaxf(mx1, __shfl_xor_sync(0xffffffffu, mx1, 2));
            float mn0 = fmaxf(m0, mx0), mn1 = fmaxf(m1, mx1);
            float corr0 = __expf(m0 - mn0), corr1 = __expf(m1 - mn1);
            m0 = mn0;
            m1 = mn1;
            float s0 = 0.f, s1 = 0.f;
#pragma unroll
            for (int nb = 0; nb < 8; nb++) {
                float* cc = sacc[nb];
                cc[0] = __expf(cc[0] - mn0);
                cc[1] = __expf(cc[1] - mn0);
                cc[2] = __expf(cc[2] - mn1);
                cc[3] = __expf(cc[3] - mn1);
                s0 += cc[0] + cc[1];
                s1 += cc[2] + cc[3];
            }
            s0 += __shfl_xor_sync(0xffffffffu, s0, 1);
            s0 += __shfl_xor_sync(0xffffffffu, s0, 2);
            s1 += __shfl_xor_sync(0xffffffffu, s1, 1);
            s1 += __shfl_xor_sync(0xffffffffu, s1, 2);
            l0 = l0 * corr0 + s0;
            l1 = l1 * corr1 + s1;
#pragma unroll
            for (int f = 0; f < 16; f++) {
                oacc[f][0] *= corr0;
                oacc[f][1] *= corr0;
                oacc[f][2] *= corr1;
                oacc[f][3] *= corr1;
            }
#pragma unroll
            for (int g2 = 0; g2 < 4; g2++) {
                float* p0 = sacc[2 * g2];
                float* p1 = sacc[2 * g2 + 1];
                uint32_t aph[4], apl[4];
                pack2(p0[0], p0[1], aph[0], apl[0]);
                pack2(p0[2], p0[3], aph[1], apl[1]);
                pack2(p1[0], p1[1], aph[2], apl[2]);
                pack2(p1[2], p1[3], aph[3], apl[3]);
#pragma unroll
                for (int gd = 0; gd < 8; gd++) {
                    uint32_t voff = (g2 * 16 + lr) * ASTRB + (gd * 16 + lc) * 2;
                    uint32_t vh_[4], vl_[4];
                    ldsm_x4_t(kvb + KV_VH + voff, vh_[0], vh_[1], vh_[2], vh_[3]);
                    ldsm_x4_t(kvb + KV_VL + voff, vl_[0], vl_[1], vl_[2], vl_[3]);
                    float* o0 = oacc[2 * gd];
                    float* o1 = oacc[2 * gd + 1];
                    mma16816(o0, aph[0], aph[1], aph[2], aph[3], vh_[0], vh_[1]);
                    mma16816(o0, aph[0], aph[1], aph[2], aph[3], vl_[0], vl_[1]);
                    mma16816(o0, apl[0], apl[1], apl[2], apl[3], vh_[0], vh_[1]);
                    mma16816(o1, aph[0], aph[1], aph[2], aph[3], vh_[2], vh_[3]);
                    mma16816(o1, aph[0], aph[1], aph[2], aph[3], vl_[2], vl_[3]);
                    mma16816(o1, apl[0], apl[1], apl[2], apl[3], vh_[2], vh_[3]);
                }
            }
        }
        __syncthreads();
    }

    float li0 = 1.f / l0, li1 = 1.f / l1;
    const int orow0 = qrow_g + lgrp;
#pragma unroll
    for (int nt = 0; nt < 16; nt++) {
        float v0 = oacc[nt][0] * li0, v1 = oacc[nt][1] * li0;
        float v2 = oacc[nt][2] * li1, v3 = oacc[nt][3] * li1;
        int col = h * HDIM + nt * 8 + 2 * lq;
        __nv_bfloat162 h2, l2;
        split2(v0, v1, h2, l2);
        *(__nv_bfloat162*)(oh + (size_t)orow0 * DMODEL + col) = h2;
        *(__nv_bfloat162*)(ol + (size_t)orow0 * DMODEL + col) = l2;
        split2(v2, v3, h2, l2);
        *(__nv_bfloat162*)(oh + (size_t)(orow0 + 8) * DMODEL + col) = h2;
        *(__nv_bfloat162*)(ol + (size_t)(orow0 + 8) * DMODEL + col) = l2;
    }
}

// ===================== launch =====================
extern "C" void kernel_launch(void* const* d_in, const int* in_sizes, int n_in,
                              void* d_out, int out_size) {
    const float* hidden = (const float*)d_in[0];
    const float* fcos = (const float*)d_in[2];
    const float* fsin = (const float*)d_in[3];
    const float* ln1 = (const float*)d_in[4];
    const float* wq = (const float*)d_in[5];
    const float* wk = (const float*)d_in[6];
    const float* wv = (const float*)d_in[7];
    const float* wo = (const float*)d_in[8];
    const float* ln2 = (const float*)d_in[9];
    const float* gate_w = (const float*)d_in[10];
    const float* up_w = (const float*)d_in[11];
    const float* down_w = (const float*)d_in[12];
    float* out = (float*)d_out;

    float *qkv, *hbuf, *gu;
    cudaGetSymbolAddress((void**)&qkv, g_qkv);
    cudaGetSymbolAddress((void**)&hbuf, g_h);
    cudaGetSymbolAddress((void**)&gu, g_gu);
    __nv_bfloat16 *xnh, *xnl, *qh, *ql, *kkh, *kkl, *vvh, *vvl, *attnh, *attnl, *x2h, *x2l, *ffh,
        *ffl;
    cudaGetSymbolAddress((void**)&xnh, g_xnh);
    cudaGetSymbolAddress((void**)&xnl, g_xnl);
    cudaGetSymbolAddress((void**)&qh, g_qh);
    cudaGetSymbolAddress((void**)&ql, g_ql);
    cudaGetSymbolAddress((void**)&kkh, g_kh);
    cudaGetSymbolAddress((void**)&kkl, g_kl);
    cudaGetSymbolAddress((void**)&vvh, g_vh);
    cudaGetSymbolAddress((void**)&vvl, g_vl);
    cudaGetSymbolAddress((void**)&attnh, g_attnh);
    cudaGetSymbolAddress((void**)&attnl, g_attnl);
    cudaGetSymbolAddress((void**)&x2h, g_x2h);
    cudaGetSymbolAddress((void**)&x2l, g_x2l);
    cudaGetSymbolAddress((void**)&ffh, g_ffh);
    cudaGetSymbolAddress((void**)&ffl, g_ffl);
    __nv_bfloat16 *wqkvth, *wqkvtl, *woth, *wotl, *guth, *gutl, *dth, *dtl;
    cudaGetSymbolAddress((void**)&wqkvth, g_wqkvth);
    cudaGetSymbolAddress((void**)&wqkvtl, g_wqkvtl);
    cudaGetSymbolAddress((void**)&woth, g_woth);
    cudaGetSymbolAddress((void**)&wotl, g_wotl);
    cudaGetSymbolAddress((void**)&guth, g_guth);
    cudaGetSymbolAddress((void**)&gutl, g_gutl);
    cudaGetSymbolAddress((void**)&dth, g_dth);
    cudaGetSymbolAddress((void**)&dtl, g_dtl);

    cudaFuncSetAttribute(gemm_bf16x3_kernel<0>, cudaFuncAttributeMaxDynamicSharedMemorySize,
                         GEMM_SMEM);
    cudaFuncSetAttribute(gemm_bf16x3_kernel<1>, cudaFuncAttributeMaxDynamicSharedMemorySize,
                         GEMM_SMEM);
    cudaFuncSetAttribute(flash_attn_bf16_kernel, cudaFuncAttributeMaxDynamicSharedMemorySize,
                         ATT_SMEM);

    dim3 tb(32, 8);
    transpose_split_kernel<<<dim3(DMODEL / 32, DMODEL / 32), tb>>>(wq, wqkvth, wqkvtl, DMODEL,
                                                                   DMODEL);
    transpose_split_kernel<<<dim3((NKVH * HDIM) / 32, DMODEL / 32), tb>>>(
        wk, wqkvth + (size_t)DMODEL * DMODEL, wqkvtl + (size_t)DMODEL * DMODEL, DMODEL,
        NKVH * HDIM);
    transpose_split_kernel<<<dim3((NKVH * HDIM) / 32, DMODEL / 32), tb>>>(
        wv, wqkvth + (size_t)(DMODEL + NKVH * HDIM) * DMODEL,
        wqkvtl + (size_t)(DMODEL + NKVH * HDIM) * DMODEL, DMODEL, NKVH * HDIM);
    transpose_split_kernel<<<dim3(DMODEL / 32, DMODEL / 32), tb>>>(wo, woth, wotl, DMODEL, DMODEL);
    transpose_split_kernel<<<dim3(DFF / 32, DMODEL / 32), tb>>>(gate_w, guth, gutl, DMODEL, DFF);
    transpose_split_kernel<<<dim3(DFF / 32, DMODEL / 32), tb>>>(
        up_w, guth + (size_t)DFF * DMODEL, gutl + (size_t)DFF * DMODEL, DMODEL, DFF);
    transpose_split_kernel<<<dim3(DMODEL / 32, DFF / 32), tb>>>(down_w, dth, dtl, DFF, DMODEL);

    rmsnorm_split_kernel<<<SEQ, 256>>>(hidden, ln1, xnh, xnl);
    gemm_bf16x3_kernel<0><<<dim3(NQKV / BN, SEQ / BM), 256, GEMM_SMEM>>>(
        xnh, xnl, wqkvth, wqkvtl, qkv, qkv, SEQ, NQKV, DMODEL);
    rope_l2_split_kernel<<<dim3(SEQ, NHEADS), 64>>>(qkv, fcos, fsin, qh, ql, 0, NHEADS);
    rope_l2_split_kernel<<<dim3(SEQ, NKVH), 64>>>(qkv, fcos, fsin, kkh, kkl, DMODEL, NKVH);
    vsplit_kernel<<<SEQ * 256 / 256, 256>>>(qkv, vvh, vvl);
    flash_attn_bf16_kernel<<<dim3(SEQ / 128, NHEADS), 256, ATT_SMEM>>>(qh, ql, kkh, kkl, vvh, vvl,
                                                                       attnh, attnl);
    gemm_bf16x3_kernel<1><<<dim3(DMODEL / BN, SEQ / BM), 256, GEMM_SMEM>>>(
        attnh, attnl, woth, wotl, hbuf, hidden, SEQ, DMODEL, DMODEL);
    rmsnorm_split_kernel<<<SEQ, 256>>>(hbuf, ln2, x2h, x2l);
    gemm_bf16x3_kernel<0><<<dim3(NGU / BN, SEQ / BM), 256, GEMM_SMEM>>>(
        x2h, x2l, guth, gutl, gu, gu, SEQ, NGU, DMODEL);
    silu_mul_split_kernel<<<4096, 256>>>(gu, ffh, ffl);
    gemm_bf16x3_kernel<1><<<dim3(DMODEL / BN, SEQ / BM), 256, GEMM_SMEM>>>(
        ffh, ffl, dth, dtl, out, hbuf, SEQ, DMODEL, DFF);
}